// round 1
// baseline (speedup 1.0000x reference)
#include <cuda_runtime.h>
#include <math.h>

#define BATCH 32
#define HH 32
#define WW_ 32
#define L 1024
#define DIM 384
#define NH 12
#define HD 32
#define WS 7
#define NWIN 800            // 32 * 25
#define NTOK 49
#define TOKENS (NWIN * NTOK)   // 39200
#define BL (BATCH * L)         // 32768
#define FFN (4 * DIM)          // 1536
#define EPSV 1e-5f

// ---------------- scratch (device globals; no allocation) ----------------
__device__ float g_xn[(size_t)TOKENS * DIM];      // LN1 output, windowed
__device__ float g_qkv[(size_t)TOKENS * 3 * DIM]; // qkv
__device__ float g_ao[(size_t)TOKENS * DIM];      // attention output (pre-proj)
__device__ float g_proj[(size_t)TOKENS * DIM];    // proj output, windowed
__device__ float g_xa[(size_t)BL * DIM];          // after attn residual (B,L,C)
__device__ float g_xb[(size_t)BL * DIM];          // after conv+BN (B,L,C)
__device__ float g_xn2[(size_t)BL * DIM];         // LN2 output
__device__ float g_h[(size_t)BL * FFN];           // fc1+gelu output

// ---------------- block reduce (128 threads) ----------------
__device__ __forceinline__ void blockReduce2_128(float& a, float& b) {
    __shared__ float sa[4], sb[4];
    int lane = threadIdx.x & 31, wid = threadIdx.x >> 5;
    #pragma unroll
    for (int o = 16; o > 0; o >>= 1) {
        a += __shfl_down_sync(0xffffffffu, a, o);
        b += __shfl_down_sync(0xffffffffu, b, o);
    }
    if (lane == 0) { sa[wid] = a; sb[wid] = b; }
    __syncthreads();
    if (threadIdx.x == 0) {
        a = sa[0] + sa[1] + sa[2] + sa[3];
        b = sb[0] + sb[1] + sb[2] + sb[3];
        sa[0] = a; sb[0] = b;
    }
    __syncthreads();
    a = sa[0]; b = sb[0];
    __syncthreads();
}

// ---------------- LN1 + window partition ----------------
// block per (window, token); 128 threads; 3 channels per thread
__global__ void ln1_window_kernel(const float* __restrict__ x,
                                  const float* __restrict__ w,
                                  const float* __restrict__ b) {
    int g = blockIdx.x;              // 0..39199
    int win = g / NTOK, t = g % NTOK;
    int bb = win / 25, wrem = win % 25;
    int wh = wrem / 5, wwi = wrem % 5;
    int i = t / WS, j = t % WS;
    int row = wh * WS + i, col = wwi * WS + j;
    bool valid = (row < HH) && (col < WW_);
    const float* xp = x + ((size_t)bb * L + row * WW_ + col) * DIM;
    int tid = threadIdx.x;
    float vals[3];
    float s = 0.f, sq = 0.f;
    #pragma unroll
    for (int c = 0; c < 3; ++c) {
        float v = valid ? xp[tid + c * 128] : 0.f;
        vals[c] = v; s += v; sq += v * v;
    }
    blockReduce2_128(s, sq);
    float mu = s * (1.f / DIM);
    float var = sq * (1.f / DIM) - mu * mu;
    float inv = rsqrtf(var + EPSV);
    float* op = g_xn + (size_t)g * DIM;
    #pragma unroll
    for (int c = 0; c < 3; ++c) {
        int idx = tid + c * 128;
        op[idx] = (vals[c] - mu) * inv * w[idx] + b[idx];
    }
}

// ---------------- LN2 (contiguous tokens) ----------------
__global__ void ln2_kernel(const float* __restrict__ w,
                           const float* __restrict__ b) {
    int g = blockIdx.x;              // 0..32767
    const float* xp = g_xb + (size_t)g * DIM;
    int tid = threadIdx.x;
    float vals[3];
    float s = 0.f, sq = 0.f;
    #pragma unroll
    for (int c = 0; c < 3; ++c) {
        float v = xp[tid + c * 128];
        vals[c] = v; s += v; sq += v * v;
    }
    blockReduce2_128(s, sq);
    float mu = s * (1.f / DIM);
    float var = sq * (1.f / DIM) - mu * mu;
    float inv = rsqrtf(var + EPSV);
    float* op = g_xn2 + (size_t)g * DIM;
    #pragma unroll
    for (int c = 0; c < 3; ++c) {
        int idx = tid + c * 128;
        op[idx] = (vals[c] - mu) * inv * w[idx] + b[idx];
    }
}

// ---------------- SGEMM 128x128x8, 256 threads, 8x8 microtile ----------------
// C[M,N] = A[M,K] @ B[K,N] + bias[N]; EPI: 0 none, 1 gelu(exact), 2 +R
// Requires N % 128 == 0, K % 8 == 0 (holds for all uses). M bounds-checked.
template <int EPI>
__global__ void sgemm_kernel(const float* __restrict__ A,
                             const float* __restrict__ B,
                             const float* __restrict__ bias,
                             float* __restrict__ C,
                             const float* __restrict__ R,
                             int M, int N, int K) {
    __shared__ float As[8][128];
    __shared__ float Bs[8][128];
    const int tid = threadIdx.x;
    const int tx = tid % 16;      // N direction
    const int ty = tid / 16;      // M direction
    const int bx = blockIdx.x;    // N tile
    const int by = blockIdx.y;    // M tile

    float acc[8][8];
    #pragma unroll
    for (int i = 0; i < 8; ++i)
        #pragma unroll
        for (int j = 0; j < 8; ++j) acc[i][j] = 0.f;

    const int aRow = tid >> 1;            // 0..127
    const int aCol = (tid & 1) * 4;       // 0 or 4
    const int bRow = tid >> 5;            // 0..7
    const int bCol = (tid & 31) * 4;      // 0..124
    const int gARow = by * 128 + aRow;
    const bool aValid = (gARow < M);
    const float* Aptr = A + (size_t)gARow * K + aCol;
    const float* Bptr = B + (size_t)bRow * N + (size_t)bx * 128 + bCol;

    for (int k0 = 0; k0 < K; k0 += 8) {
        float4 av = make_float4(0.f, 0.f, 0.f, 0.f);
        if (aValid) av = *reinterpret_cast<const float4*>(Aptr + k0);
        As[aCol + 0][aRow] = av.x;
        As[aCol + 1][aRow] = av.y;
        As[aCol + 2][aRow] = av.z;
        As[aCol + 3][aRow] = av.w;
        float4 bv = *reinterpret_cast<const float4*>(Bptr + (size_t)k0 * N);
        *reinterpret_cast<float4*>(&Bs[bRow][bCol]) = bv;
        __syncthreads();
        #pragma unroll
        for (int kk = 0; kk < 8; ++kk) {
            float ar[8], br[8];
            #pragma unroll
            for (int i = 0; i < 4; ++i) {
                float4 t4 = *reinterpret_cast<const float4*>(&As[kk][ty * 8 + i * 4]);
                ar[i * 4 + 0] = t4.x; ar[i * 4 + 1] = t4.y; ar[i * 4 + 2] = t4.z; ar[i * 4 + 3] = t4.w;
                i = i; // keep loop simple
                if (i == 1) break;
            }
            {
                float4 t4 = *reinterpret_cast<const float4*>(&As[kk][ty * 8]);
                ar[0] = t4.x; ar[1] = t4.y; ar[2] = t4.z; ar[3] = t4.w;
                t4 = *reinterpret_cast<const float4*>(&As[kk][ty * 8 + 4]);
                ar[4] = t4.x; ar[5] = t4.y; ar[6] = t4.z; ar[7] = t4.w;
            }
            {
                float4 t4 = *reinterpret_cast<const float4*>(&Bs[kk][tx * 8]);
                br[0] = t4.x; br[1] = t4.y; br[2] = t4.z; br[3] = t4.w;
                t4 = *reinterpret_cast<const float4*>(&Bs[kk][tx * 8 + 4]);
                br[4] = t4.x; br[5] = t4.y; br[6] = t4.z; br[7] = t4.w;
            }
            #pragma unroll
            for (int i = 0; i < 8; ++i)
                #pragma unroll
                for (int j = 0; j < 8; ++j)
                    acc[i][j] += ar[i] * br[j];
        }
        __syncthreads();
    }

    #pragma unroll
    for (int i = 0; i < 8; ++i) {
        int row = by * 128 + ty * 8 + i;
        if (row >= M) continue;
        #pragma unroll
        for (int j = 0; j < 8; j += 4) {
            int col = bx * 128 + tx * 8 + j;
            float4 b4 = *reinterpret_cast<const float4*>(bias + col);
            float4 c4;
            c4.x = acc[i][j + 0] + b4.x;
            c4.y = acc[i][j + 1] + b4.y;
            c4.z = acc[i][j + 2] + b4.z;
            c4.w = acc[i][j + 3] + b4.w;
            if (EPI == 1) {
                c4.x = 0.5f * c4.x * (1.f + erff(c4.x * 0.70710678118654752f));
                c4.y = 0.5f * c4.y * (1.f + erff(c4.y * 0.70710678118654752f));
                c4.z = 0.5f * c4.z * (1.f + erff(c4.z * 0.70710678118654752f));
                c4.w = 0.5f * c4.w * (1.f + erff(c4.w * 0.70710678118654752f));
            }
            if (EPI == 2) {
                float4 r4 = *reinterpret_cast<const float4*>(R + (size_t)row * N + col);
                c4.x += r4.x; c4.y += r4.y; c4.z += r4.z; c4.w += r4.w;
            }
            *reinterpret_cast<float4*>(C + (size_t)row * N + col) = c4;
        }
    }
}

// ---------------- fused windowed attention ----------------
// block per (window, head); 256 threads
__global__ void attn_kernel(const float* __restrict__ attn_bias,
                            const int* __restrict__ bias_idxs) {
    int w = blockIdx.x;  // 0..799
    int h = blockIdx.y;  // 0..11
    __shared__ float q[NTOK * HD];
    __shared__ float k[NTOK * HD];
    __shared__ float v[NTOK * HD];
    __shared__ float s[NTOK * 50];
    __shared__ float brow[NTOK];
    int tid = threadIdx.x;
    const float* base = g_qkv + (size_t)w * NTOK * (3 * DIM);
    for (int i = tid; i < NTOK * HD; i += 256) {
        int t = i / HD, d = i % HD;
        const float* p = base + (size_t)t * (3 * DIM) + h * 96 + d;
        q[i] = p[0];
        k[i] = p[32];
        v[i] = p[64];
    }
    if (tid < NTOK) brow[tid] = attn_bias[h * NTOK + tid];
    __syncthreads();
    const float scale = 0.1767766952966369f; // 32^-0.5
    for (int i = tid; i < NTOK * NTOK; i += 256) {
        int n = i / NTOK, m = i % NTOK;
        float acc = 0.f;
        #pragma unroll
        for (int d = 0; d < HD; ++d) acc += q[n * HD + d] * k[m * HD + d];
        s[n * 50 + m] = acc * scale + brow[bias_idxs[i]];
    }
    __syncthreads();
    if (tid < NTOK) {
        float mx = -1e30f;
        #pragma unroll 7
        for (int m = 0; m < NTOK; ++m) mx = fmaxf(mx, s[tid * 50 + m]);
        float sum = 0.f;
        #pragma unroll 7
        for (int m = 0; m < NTOK; ++m) {
            float e = expf(s[tid * 50 + m] - mx);
            s[tid * 50 + m] = e;
            sum += e;
        }
        float invs = 1.f / sum;
        #pragma unroll 7
        for (int m = 0; m < NTOK; ++m) s[tid * 50 + m] *= invs;
    }
    __syncthreads();
    for (int i = tid; i < NTOK * HD; i += 256) {
        int n = i / HD, d = i % HD;
        float acc = 0.f;
        #pragma unroll 7
        for (int m = 0; m < NTOK; ++m) acc += s[n * 50 + m] * v[m * HD + d];
        g_ao[((size_t)w * NTOK + n) * DIM + h * HD + d] = acc;
    }
}

// ---------------- un-window + residual add ----------------
// thread per float4 of (B, L, C)
__global__ void scatter_kernel(const float* __restrict__ x) {
    size_t idx = (size_t)blockIdx.x * blockDim.x + threadIdx.x;
    size_t total = (size_t)BL * (DIM / 4);
    if (idx >= total) return;
    int c4 = idx % (DIM / 4);
    size_t l_ = idx / (DIM / 4);
    int l = (int)(l_ % L);
    int bb = (int)(l_ / L);
    int row = l / WW_, col = l % WW_;
    int win = bb * 25 + (row / WS) * 5 + (col / WS);
    int t = (row % WS) * WS + (col % WS);
    float4 pv = *reinterpret_cast<const float4*>(
        g_proj + ((size_t)win * NTOK + t) * DIM + c4 * 4);
    float4 xv = *reinterpret_cast<const float4*>(x + idx * 4);
    pv.x += xv.x; pv.y += xv.y; pv.z += xv.z; pv.w += xv.w;
    *reinterpret_cast<float4*>(g_xa + idx * 4) = pv;
}

// ---------------- depthwise 3x3 conv + BN (inference) ----------------
__global__ void conv_bn_kernel(const float* __restrict__ cw,
                               const float* __restrict__ bg,
                               const float* __restrict__ bb_,
                               const float* __restrict__ bm,
                               const float* __restrict__ bv) {
    size_t idx = (size_t)blockIdx.x * blockDim.x + threadIdx.x;
    size_t total = (size_t)BL * DIM;
    if (idx >= total) return;
    int c = idx % DIM;
    size_t l_ = idx / DIM;
    int l = (int)(l_ % L);
    int bb = (int)(l_ / L);
    int row = l / WW_, col = l % WW_;
    float acc = 0.f;
    #pragma unroll
    for (int dh = -1; dh <= 1; ++dh) {
        #pragma unroll
        for (int dw = -1; dw <= 1; ++dw) {
            int r = row + dh, cc = col + dw;
            if (r >= 0 && r < HH && cc >= 0 && cc < WW_) {
                acc += g_xa[((size_t)bb * L + r * WW_ + cc) * DIM + c] *
                       cw[c * 9 + (dh + 1) * 3 + (dw + 1)];
            }
        }
    }
    float inv = rsqrtf(bv[c] + EPSV);
    g_xb[idx] = (acc - bm[c]) * inv * bg[c] + bb_[c];
}

// ---------------- launch ----------------
extern "C" void kernel_launch(void* const* d_in, const int* in_sizes, int n_in,
                              void* d_out, int out_size) {
    const float* x       = (const float*)d_in[0];
    const float* ln1_w   = (const float*)d_in[1];
    const float* ln1_b   = (const float*)d_in[2];
    const float* qkv_w   = (const float*)d_in[3];
    const float* qkv_b   = (const float*)d_in[4];
    const float* proj_w  = (const float*)d_in[5];
    const float* proj_b  = (const float*)d_in[6];
    const float* attn_bias = (const float*)d_in[7];
    const int*   bias_idxs = (const int*)d_in[8];
    const float* conv_w  = (const float*)d_in[9];
    const float* bn_g    = (const float*)d_in[10];
    const float* bn_b    = (const float*)d_in[11];
    const float* bn_m    = (const float*)d_in[12];
    const float* bn_v    = (const float*)d_in[13];
    const float* ln2_w   = (const float*)d_in[14];
    const float* ln2_b   = (const float*)d_in[15];
    const float* fc1_w   = (const float*)d_in[16];
    const float* fc1_b   = (const float*)d_in[17];
    const float* fc2_w   = (const float*)d_in[18];
    const float* fc2_b   = (const float*)d_in[19];
    float* out = (float*)d_out;

    float* xn  = nullptr; cudaGetSymbolAddress((void**)&xn,  g_xn);
    float* qkv = nullptr; cudaGetSymbolAddress((void**)&qkv, g_qkv);
    float* ao  = nullptr; cudaGetSymbolAddress((void**)&ao,  g_ao);
    float* pj  = nullptr; cudaGetSymbolAddress((void**)&pj,  g_proj);
    float* xb  = nullptr; cudaGetSymbolAddress((void**)&xb,  g_xb);
    float* xn2 = nullptr; cudaGetSymbolAddress((void**)&xn2, g_xn2);
    float* hbuf = nullptr; cudaGetSymbolAddress((void**)&hbuf, g_h);

    // 1) LN1 + window partition
    ln1_window_kernel<<<TOKENS, 128>>>(x, ln1_w, ln1_b);

    // 2) qkv = xn @ qkv_w + qkv_b   [39200 x 1152]
    {
        dim3 grid((3 * DIM) / 128, (TOKENS + 127) / 128);
        sgemm_kernel<0><<<grid, 256>>>(xn, qkv_w, qkv_b, qkv, nullptr,
                                       TOKENS, 3 * DIM, DIM);
    }

    // 3) windowed attention
    {
        dim3 grid(NWIN, NH);
        attn_kernel<<<grid, 256>>>(attn_bias, bias_idxs);
    }

    // 4) proj   [39200 x 384]
    {
        dim3 grid(DIM / 128, (TOKENS + 127) / 128);
        sgemm_kernel<0><<<grid, 256>>>(ao, proj_w, proj_b, pj, nullptr,
                                       TOKENS, DIM, DIM);
    }

    // 5) un-window + residual
    {
        size_t total = (size_t)BL * (DIM / 4);
        scatter_kernel<<<(unsigned)((total + 255) / 256), 256>>>(x);
    }

    // 6) depthwise conv + BN
    {
        size_t total = (size_t)BL * DIM;
        conv_bn_kernel<<<(unsigned)((total + 255) / 256), 256>>>(conv_w, bn_g, bn_b, bn_m, bn_v);
    }

    // 7) LN2
    ln2_kernel<<<BL, 128>>>(ln2_w, ln2_b);

    // 8) fc1 + gelu   [32768 x 1536]
    {
        dim3 grid(FFN / 128, BL / 128);
        sgemm_kernel<1><<<grid, 256>>>(xn2, fc1_w, fc1_b, hbuf, nullptr,
                                       BL, FFN, DIM);
    }

    // 9) fc2 + residual -> out   [32768 x 384]
    {
        dim3 grid(DIM / 128, BL / 128);
        sgemm_kernel<2><<<grid, 256>>>(hbuf, fc2_w, fc2_b, out, xb,
                                       BL, DIM, FFN);
    }
}

// round 4
// speedup vs baseline: 2.0109x; 2.0109x over previous
#include <cuda_runtime.h>
#include <cuda_bf16.h>
#include <math.h>
#include <stdint.h>

#define BATCH 32
#define HH 32
#define WW_ 32
#define L 1024
#define DIM 384
#define NH 12
#define HD 32
#define WS 7
#define NWIN 800
#define NTOK 49
#define TOKENS (NWIN * NTOK)   // 39200
#define MPAD 39296             // padded to multiple of 128
#define BL (BATCH * L)         // 32768
#define FFN (4 * DIM)          // 1536
#define EPSV 1e-5f

// ---------------- scratch (device globals; no allocation) ----------------
__device__ float g_xn[(size_t)MPAD * DIM];       // LN1 out (windowed), tf32-rounded fp32
__device__ float g_qkv[(size_t)MPAD * 3 * DIM];  // qkv fp32
__device__ float g_ao[(size_t)MPAD * DIM];       // attn out, tf32-rounded
__device__ float g_proj[(size_t)MPAD * DIM];     // proj out fp32
__device__ float g_xa[(size_t)BL * DIM];         // after attn residual
__device__ float g_xb[(size_t)BL * DIM];         // after conv+BN
__device__ float g_xn2[(size_t)BL * DIM];        // LN2 out, tf32-rounded
__device__ float g_h[(size_t)BL * FFN];          // fc1+gelu out, tf32-rounded
// transposed tf32-rounded weights: Wt[n*K + k] = W[k*N + n]
__device__ float g_wq[(size_t)3 * DIM * DIM];
__device__ float g_wp[(size_t)DIM * DIM];
__device__ float g_w1[(size_t)FFN * DIM];
__device__ float g_w2[(size_t)DIM * FFN];

// ================= helpers =================
__device__ __forceinline__ uint32_t s2u(const void* p) {
    uint32_t a;
    asm("{ .reg .u64 t; cvta.to.shared.u64 t, %1; cvt.u32.u64 %0, t; }" : "=r"(a) : "l"(p));
    return a;
}
__device__ __forceinline__ float tf32r(float x) {
    float y;
    asm("cvt.rna.tf32.f32 %0, %1;" : "=f"(y) : "f"(x));
    return y;
}
__device__ __forceinline__ void cp_async16(uint32_t dst, const void* src) {
    asm volatile("cp.async.cg.shared.global [%0], [%1], 16;" :: "r"(dst), "l"(src) : "memory");
}
__device__ __forceinline__ void cp_commit() {
    asm volatile("cp.async.commit_group;" ::: "memory");
}
template <int N>
__device__ __forceinline__ void cp_wait() {
    asm volatile("cp.async.wait_group %0;" :: "n"(N) : "memory");
}
__device__ __forceinline__ void mma_tf32(float* c, const uint32_t* a, const uint32_t* b) {
    asm volatile("mma.sync.aligned.m16n8k8.row.col.f32.tf32.tf32.f32 "
                 "{%0,%1,%2,%3}, {%4,%5,%6,%7}, {%8,%9}, {%0,%1,%2,%3};"
                 : "+f"(c[0]), "+f"(c[1]), "+f"(c[2]), "+f"(c[3])
                 : "r"(a[0]), "r"(a[1]), "r"(a[2]), "r"(a[3]), "r"(b[0]), "r"(b[1]));
}

// swizzled byte offset within a 128x32-float tile (rows of 128 bytes)
__device__ __forceinline__ uint32_t swz(int row, uint32_t bytecol) {
    return (uint32_t)row * 128u + (bytecol ^ (((uint32_t)row & 7u) << 4));
}

// load one 128x32 fp32 tile (row-major, ld elems) into swizzled smem via cp.async
__device__ __forceinline__ void load_tile_async(const float* __restrict__ src, int ld,
                                                int k0, uint32_t dst, int tid) {
    #pragma unroll
    for (int i = 0; i < 4; ++i) {
        int idx = i * 256 + tid;
        int r = idx >> 3, f = idx & 7;
        cp_async16(dst + swz(r, (uint32_t)(f * 16)), src + (size_t)r * ld + k0 + f * 4);
    }
}

// ============ TF32 HMMA GEMM: C[M,N] = A[M,K] @ Bt[N,K]^T + bias ============
// EPI: 0 fp32 out; 1 gelu -> tf32-rounded fp32 out; 2 +R residual -> fp32 out
// N % 128 == 0, K % 32 == 0. A/Bt must have >= ceil(M/128)*128 rows allocated.
#define MM_SMEM_BYTES 65536
template <int EPI>
__global__ void __launch_bounds__(256) mm_kernel(const float* __restrict__ A,
                                                 const float* __restrict__ Bt,
                                                 const float* __restrict__ bias,
                                                 float* __restrict__ Cout,
                                                 const float* __restrict__ R,
                                                 int M, int N, int K) {
    extern __shared__ char smem[];
    const int tid = threadIdx.x;
    const int wid = tid >> 5, lane = tid & 31;
    const int bx = blockIdx.x, by = blockIdx.y;
    const uint32_t sb = s2u(smem);
    const uint32_t asb[2] = { sb, sb + 16384 };
    const uint32_t bsb[2] = { sb + 32768, sb + 49152 };

    const float* Abase = A + (size_t)by * 128 * K;
    const float* Bbase = Bt + (size_t)bx * 128 * K;
    const int nk = K >> 5;

    const int warp_m = (wid >> 2) * 64;   // 0 or 64
    const int warp_n = (wid & 3) * 32;    // 0,32,64,96
    const int tg = lane >> 2;             // 0..7
    const int tq = lane & 3;              // 0..3

    float acc[4][4][4];
    #pragma unroll
    for (int i = 0; i < 4; ++i)
        #pragma unroll
        for (int j = 0; j < 4; ++j)
            #pragma unroll
            for (int q = 0; q < 4; ++q) acc[i][j][q] = 0.f;

    load_tile_async(Abase, K, 0, asb[0], tid);
    load_tile_async(Bbase, K, 0, bsb[0], tid);
    cp_commit();

    for (int c = 0; c < nk; ++c) {
        int cur = c & 1;
        if (c + 1 < nk) {
            load_tile_async(Abase, K, (c + 1) * 32, asb[cur ^ 1], tid);
            load_tile_async(Bbase, K, (c + 1) * 32, bsb[cur ^ 1], tid);
            cp_commit();
            cp_wait<1>();
        } else {
            cp_wait<0>();
        }
        __syncthreads();

        #pragma unroll
        for (int ks = 0; ks < 4; ++ks) {
            const uint32_t c0 = (uint32_t)((ks * 8 + tq) * 4);
            uint32_t a[4][4];
            #pragma unroll
            for (int mt = 0; mt < 4; ++mt) {
                int r0 = warp_m + mt * 16 + tg;
                int r1 = r0 + 8;
                a[mt][0] = *(const uint32_t*)(smem + (asb[cur] - sb) + swz(r0, c0));
                a[mt][1] = *(const uint32_t*)(smem + (asb[cur] - sb) + swz(r1, c0));
                a[mt][2] = *(const uint32_t*)(smem + (asb[cur] - sb) + swz(r0, c0 + 16));
                a[mt][3] = *(const uint32_t*)(smem + (asb[cur] - sb) + swz(r1, c0 + 16));
            }
            uint32_t b[4][2];
            #pragma unroll
            for (int nt = 0; nt < 4; ++nt) {
                int nr = warp_n + nt * 8 + tg;
                b[nt][0] = *(const uint32_t*)(smem + (bsb[cur] - sb) + swz(nr, c0));
                b[nt][1] = *(const uint32_t*)(smem + (bsb[cur] - sb) + swz(nr, c0 + 16));
            }
            #pragma unroll
            for (int mt = 0; mt < 4; ++mt)
                #pragma unroll
                for (int nt = 0; nt < 4; ++nt)
                    mma_tf32(acc[mt][nt], a[mt], b[nt]);
        }
        __syncthreads();
    }

    // ---- epilogue: fragments -> gmem ----
    const int erow = lane >> 2;          // 0..7
    const int ecol = (lane & 3) * 2;     // 0,2,4,6
    #pragma unroll
    for (int nt = 0; nt < 4; ++nt) {
        int gcol = bx * 128 + warp_n + nt * 8 + ecol;
        float b0 = bias[gcol], b1 = bias[gcol + 1];
        #pragma unroll
        for (int mt = 0; mt < 4; ++mt) {
            #pragma unroll
            for (int h = 0; h < 2; ++h) {
                int grow = by * 128 + warp_m + mt * 16 + erow + h * 8;
                if (grow >= M) continue;
                float v0 = acc[mt][nt][h * 2 + 0] + b0;
                float v1 = acc[mt][nt][h * 2 + 1] + b1;
                if (EPI == 1) {
                    v0 = 0.5f * v0 * (1.f + erff(v0 * 0.70710678118654752f));
                    v1 = 0.5f * v1 * (1.f + erff(v1 * 0.70710678118654752f));
                    v0 = tf32r(v0);
                    v1 = tf32r(v1);
                } else if (EPI == 2) {
                    float2 r2 = *reinterpret_cast<const float2*>(R + (size_t)grow * N + gcol);
                    v0 += r2.x; v1 += r2.y;
                }
                float2 o = make_float2(v0, v1);
                *reinterpret_cast<float2*>(Cout + (size_t)grow * N + gcol) = o;
            }
        }
    }
}

// ---------------- weight transpose + tf32 rounding ----------------
__global__ void wt_kernel(const float* __restrict__ W, float* __restrict__ Wt, int K, int N) {
    int idx = blockIdx.x * 256 + threadIdx.x;
    if (idx >= K * N) return;
    int k = idx / N, n = idx % N;
    Wt[(size_t)n * K + k] = tf32r(W[idx]);
}

// ---------------- block reduce (128 threads) ----------------
__device__ __forceinline__ void blockReduce2_128(float& a, float& b) {
    __shared__ float sa[4], sb_[4];
    int lane = threadIdx.x & 31, wid = threadIdx.x >> 5;
    #pragma unroll
    for (int o = 16; o > 0; o >>= 1) {
        a += __shfl_down_sync(0xffffffffu, a, o);
        b += __shfl_down_sync(0xffffffffu, b, o);
    }
    if (lane == 0) { sa[wid] = a; sb_[wid] = b; }
    __syncthreads();
    if (threadIdx.x == 0) {
        a = sa[0] + sa[1] + sa[2] + sa[3];
        b = sb_[0] + sb_[1] + sb_[2] + sb_[3];
        sa[0] = a; sb_[0] = b;
    }
    __syncthreads();
    a = sa[0]; b = sb_[0];
    __syncthreads();
}

// ---------------- LN1 + window partition -> tf32-rounded fp32 ----------------
__global__ void ln1_window_kernel(const float* __restrict__ x,
                                  const float* __restrict__ w,
                                  const float* __restrict__ b) {
    int g = blockIdx.x;
    int win = g / NTOK, t = g % NTOK;
    int bb = win / 25, wrem = win % 25;
    int wh = wrem / 5, wwi = wrem % 5;
    int i = t / WS, j = t % WS;
    int row = wh * WS + i, col = wwi * WS + j;
    bool valid = (row < HH) && (col < WW_);
    const float* xp = x + ((size_t)bb * L + row * WW_ + col) * DIM;
    int tid = threadIdx.x;
    float vals[3];
    float s = 0.f, sq = 0.f;
    #pragma unroll
    for (int c = 0; c < 3; ++c) {
        float v = valid ? xp[tid + c * 128] : 0.f;
        vals[c] = v; s += v; sq += v * v;
    }
    blockReduce2_128(s, sq);
    float mu = s * (1.f / DIM);
    float var = sq * (1.f / DIM) - mu * mu;
    float inv = rsqrtf(var + EPSV);
    float* op = g_xn + (size_t)g * DIM;
    #pragma unroll
    for (int c = 0; c < 3; ++c) {
        int idx = tid + c * 128;
        op[idx] = tf32r((vals[c] - mu) * inv * w[idx] + b[idx]);
    }
}

// ---------------- LN2 -> tf32-rounded fp32 ----------------
__global__ void ln2_kernel(const float* __restrict__ w,
                           const float* __restrict__ b) {
    int g = blockIdx.x;
    const float* xp = g_xb + (size_t)g * DIM;
    int tid = threadIdx.x;
    float vals[3];
    float s = 0.f, sq = 0.f;
    #pragma unroll
    for (int c = 0; c < 3; ++c) {
        float v = xp[tid + c * 128];
        vals[c] = v; s += v; sq += v * v;
    }
    blockReduce2_128(s, sq);
    float mu = s * (1.f / DIM);
    float var = sq * (1.f / DIM) - mu * mu;
    float inv = rsqrtf(var + EPSV);
    float* op = g_xn2 + (size_t)g * DIM;
    #pragma unroll
    for (int c = 0; c < 3; ++c) {
        int idx = tid + c * 128;
        op[idx] = tf32r((vals[c] - mu) * inv * w[idx] + b[idx]);
    }
}

// ---------------- fused windowed attention ----------------
__global__ void attn_kernel(const float* __restrict__ attn_bias,
                            const int* __restrict__ bias_idxs) {
    int w = blockIdx.x;
    int h = blockIdx.y;
    __shared__ float q[NTOK * HD];
    __shared__ float k[NTOK * HD];
    __shared__ float v[NTOK * HD];
    __shared__ float s[NTOK * 50];
    __shared__ float brow[NTOK];
    int tid = threadIdx.x;
    const float* base = g_qkv + (size_t)w * NTOK * (3 * DIM);
    for (int i = tid; i < NTOK * HD; i += 256) {
        int t = i / HD, d = i % HD;
        const float* p = base + (size_t)t * (3 * DIM) + h * 96 + d;
        q[i] = p[0];
        k[i] = p[32];
        v[i] = p[64];
    }
    if (tid < NTOK) brow[tid] = attn_bias[h * NTOK + tid];
    __syncthreads();
    const float scale = 0.1767766952966369f;
    for (int i = tid; i < NTOK * NTOK; i += 256) {
        int n = i / NTOK, m = i % NTOK;
        float acc = 0.f;
        #pragma unroll
        for (int d = 0; d < HD; ++d) acc += q[n * HD + d] * k[m * HD + d];
        s[n * 50 + m] = acc * scale + brow[bias_idxs[i]];
    }
    __syncthreads();
    if (tid < NTOK) {
        float mx = -1e30f;
        #pragma unroll 7
        for (int m = 0; m < NTOK; ++m) mx = fmaxf(mx, s[tid * 50 + m]);
        float sum = 0.f;
        #pragma unroll 7
        for (int m = 0; m < NTOK; ++m) {
            float e = expf(s[tid * 50 + m] - mx);
            s[tid * 50 + m] = e;
            sum += e;
        }
        float invs = 1.f / sum;
        #pragma unroll 7
        for (int m = 0; m < NTOK; ++m) s[tid * 50 + m] *= invs;
    }
    __syncthreads();
    for (int i = tid; i < NTOK * HD; i += 256) {
        int n = i / HD, d = i % HD;
        float acc = 0.f;
        #pragma unroll 7
        for (int m = 0; m < NTOK; ++m) acc += s[n * 50 + m] * v[m * HD + d];
        g_ao[((size_t)w * NTOK + n) * DIM + h * HD + d] = tf32r(acc);
    }
}

// ---------------- un-window + residual add ----------------
__global__ void scatter_kernel(const float* __restrict__ x) {
    size_t idx = (size_t)blockIdx.x * blockDim.x + threadIdx.x;
    size_t total = (size_t)BL * (DIM / 4);
    if (idx >= total) return;
    int c4 = idx % (DIM / 4);
    size_t l_ = idx / (DIM / 4);
    int l = (int)(l_ % L);
    int bb = (int)(l_ / L);
    int row = l / WW_, col = l % WW_;
    int win = bb * 25 + (row / WS) * 5 + (col / WS);
    int t = (row % WS) * WS + (col % WS);
    float4 pv = *reinterpret_cast<const float4*>(
        g_proj + ((size_t)win * NTOK + t) * DIM + c4 * 4);
    float4 xv = *reinterpret_cast<const float4*>(x + idx * 4);
    pv.x += xv.x; pv.y += xv.y; pv.z += xv.z; pv.w += xv.w;
    *reinterpret_cast<float4*>(g_xa + idx * 4) = pv;
}

// ---------------- depthwise 3x3 conv + BN ----------------
__global__ void conv_bn_kernel(const float* __restrict__ cw,
                               const float* __restrict__ bg,
                               const float* __restrict__ bb_,
                               const float* __restrict__ bm,
                               const float* __restrict__ bv) {
    size_t idx = (size_t)blockIdx.x * blockDim.x + threadIdx.x;
    size_t total = (size_t)BL * DIM;
    if (idx >= total) return;
    int c = idx % DIM;
    size_t l_ = idx / DIM;
    int l = (int)(l_ % L);
    int bb = (int)(l_ / L);
    int row = l / WW_, col = l % WW_;
    float acc = 0.f;
    #pragma unroll
    for (int dh = -1; dh <= 1; ++dh) {
        #pragma unroll
        for (int dw = -1; dw <= 1; ++dw) {
            int r = row + dh, cc = col + dw;
            if (r >= 0 && r < HH && cc >= 0 && cc < WW_) {
                acc += g_xa[((size_t)bb * L + r * WW_ + cc) * DIM + c] *
                       cw[c * 9 + (dh + 1) * 3 + (dw + 1)];
            }
        }
    }
    float inv = rsqrtf(bv[c] + EPSV);
    g_xb[idx] = (acc - bm[c]) * inv * bg[c] + bb_[c];
}

// ---------------- launch ----------------
extern "C" void kernel_launch(void* const* d_in, const int* in_sizes, int n_in,
                              void* d_out, int out_size) {
    const float* x         = (const float*)d_in[0];
    const float* ln1_w     = (const float*)d_in[1];
    const float* ln1_b     = (const float*)d_in[2];
    const float* qkv_w     = (const float*)d_in[3];
    const float* qkv_b     = (const float*)d_in[4];
    const float* proj_w    = (const float*)d_in[5];
    const float* proj_b    = (const float*)d_in[6];
    const float* attn_bias = (const float*)d_in[7];
    const int*   bias_idxs = (const int*)d_in[8];
    const float* conv_w    = (const float*)d_in[9];
    const float* bn_g      = (const float*)d_in[10];
    const float* bn_b      = (const float*)d_in[11];
    const float* bn_m      = (const float*)d_in[12];
    const float* bn_v      = (const float*)d_in[13];
    const float* ln2_w     = (const float*)d_in[14];
    const float* ln2_b     = (const float*)d_in[15];
    const float* fc1_w     = (const float*)d_in[16];
    const float* fc1_b     = (const float*)d_in[17];
    const float* fc2_w     = (const float*)d_in[18];
    const float* fc2_b     = (const float*)d_in[19];
    float* out = (float*)d_out;

    float *xn, *qkv, *ao, *pj, *xb, *xn2, *hbuf, *wq, *wp, *w1, *w2;
    cudaGetSymbolAddress((void**)&xn,  g_xn);
    cudaGetSymbolAddress((void**)&qkv, g_qkv);
    cudaGetSymbolAddress((void**)&ao,  g_ao);
    cudaGetSymbolAddress((void**)&pj,  g_proj);
    cudaGetSymbolAddress((void**)&xb,  g_xb);
    cudaGetSymbolAddress((void**)&xn2, g_xn2);
    cudaGetSymbolAddress((void**)&hbuf, g_h);
    cudaGetSymbolAddress((void**)&wq,  g_wq);
    cudaGetSymbolAddress((void**)&wp,  g_wp);
    cudaGetSymbolAddress((void**)&w1,  g_w1);
    cudaGetSymbolAddress((void**)&w2,  g_w2);

    cudaFuncSetAttribute(mm_kernel<0>, cudaFuncAttributeMaxDynamicSharedMemorySize, MM_SMEM_BYTES);
    cudaFuncSetAttribute(mm_kernel<1>, cudaFuncAttributeMaxDynamicSharedMemorySize, MM_SMEM_BYTES);
    cudaFuncSetAttribute(mm_kernel<2>, cudaFuncAttributeMaxDynamicSharedMemorySize, MM_SMEM_BYTES);

    // 0) weights -> transposed, tf32-rounded
    wt_kernel<<<(DIM * 3 * DIM + 255) / 256, 256>>>(qkv_w, wq, DIM, 3 * DIM);
    wt_kernel<<<(DIM * DIM + 255) / 256, 256>>>(proj_w, wp, DIM, DIM);
    wt_kernel<<<(DIM * FFN + 255) / 256, 256>>>(fc1_w, w1, DIM, FFN);
    wt_kernel<<<(FFN * DIM + 255) / 256, 256>>>(fc2_w, w2, FFN, DIM);

    // 1) LN1 + window partition
    ln1_window_kernel<<<TOKENS, 128>>>(x, ln1_w, ln1_b);

    // 2) qkv GEMM  [39200 x 1152]
    {
        dim3 grid((3 * DIM) / 128, MPAD / 128);
        mm_kernel<0><<<grid, 256, MM_SMEM_BYTES>>>(xn, wq, qkv_b, qkv, nullptr,
                                                   TOKENS, 3 * DIM, DIM);
    }

    // 3) windowed attention
    {
        dim3 grid(NWIN, NH);
        attn_kernel<<<grid, 256>>>(attn_bias, bias_idxs);
    }

    // 4) proj GEMM  [39200 x 384]
    {
        dim3 grid(DIM / 128, MPAD / 128);
        mm_kernel<0><<<grid, 256, MM_SMEM_BYTES>>>(ao, wp, proj_b, pj, nullptr,
                                                   TOKENS, DIM, DIM);
    }

    // 5) un-window + residual
    {
        size_t total = (size_t)BL * (DIM / 4);
        scatter_kernel<<<(unsigned)((total + 255) / 256), 256>>>(x);
    }

    // 6) depthwise conv + BN
    {
        size_t total = (size_t)BL * DIM;
        conv_bn_kernel<<<(unsigned)((total + 255) / 256), 256>>>(conv_w, bn_g, bn_b, bn_m, bn_v);
    }

    // 7) LN2
    ln2_kernel<<<BL, 128>>>(ln2_w, ln2_b);

    // 8) fc1 + gelu  [32768 x 1536]
    {
        dim3 grid(FFN / 128, BL / 128);
        mm_kernel<1><<<grid, 256, MM_SMEM_BYTES>>>(xn2, w1, fc1_b, hbuf, nullptr,
                                                   BL, FFN, DIM);
    }

    // 9) fc2 + residual -> out  [32768 x 384]
    {
        dim3 grid(DIM / 128, BL / 128);
        mm_kernel<2><<<grid, 256, MM_SMEM_BYTES>>>(hbuf, w2, fc2_b, out, xb,
                                                   BL, DIM, FFN);
    }
}

// round 5
// speedup vs baseline: 2.1995x; 1.0938x over previous
#include <cuda_runtime.h>
#include <cuda_bf16.h>
#include <math.h>
#include <stdint.h>

#define BATCH 32
#define HH 32
#define WW_ 32
#define L 1024
#define DIM 384
#define NH 12
#define HD 32
#define WS 7
#define NWIN 800
#define NTOK 49
#define TOKENS (NWIN * NTOK)   // 39200
#define MPAD 39296             // padded to multiple of 128
#define BL (BATCH * L)         // 32768
#define FFN (4 * DIM)          // 1536
#define EPSV 1e-5f

// ---------------- scratch (device globals; no allocation) ----------------
__device__ float g_xn[(size_t)MPAD * DIM];
__device__ float g_qkv[(size_t)MPAD * 3 * DIM];
__device__ float g_ao[(size_t)MPAD * DIM];
__device__ float g_proj[(size_t)MPAD * DIM];
__device__ float g_xa[(size_t)BL * DIM];
__device__ float g_xb[(size_t)BL * DIM];
__device__ float g_xn2[(size_t)BL * DIM];
__device__ float g_h[(size_t)BL * FFN];
__device__ float g_wq[(size_t)3 * DIM * DIM];
__device__ float g_wp[(size_t)DIM * DIM];
__device__ float g_w1[(size_t)FFN * DIM];
__device__ float g_w2[(size_t)DIM * FFN];
__device__ float g_biasf[(size_t)NH * NTOK * NTOK];   // expanded attention bias

// ================= helpers =================
__device__ __forceinline__ uint32_t s2u(const void* p) {
    uint32_t a;
    asm("{ .reg .u64 t; cvta.to.shared.u64 t, %1; cvt.u32.u64 %0, t; }" : "=r"(a) : "l"(p));
    return a;
}
__device__ __forceinline__ float tf32r(float x) {
    float y;
    asm("cvt.rna.tf32.f32 %0, %1;" : "=f"(y) : "f"(x));
    return y;
}
__device__ __forceinline__ void cp_async16(uint32_t dst, const void* src) {
    asm volatile("cp.async.cg.shared.global [%0], [%1], 16;" :: "r"(dst), "l"(src) : "memory");
}
__device__ __forceinline__ void cp_commit() {
    asm volatile("cp.async.commit_group;" ::: "memory");
}
template <int N>
__device__ __forceinline__ void cp_wait() {
    asm volatile("cp.async.wait_group %0;" :: "n"(N) : "memory");
}
__device__ __forceinline__ void mma_tf32(float* c, const uint32_t* a, const uint32_t* b) {
    asm volatile("mma.sync.aligned.m16n8k8.row.col.f32.tf32.tf32.f32 "
                 "{%0,%1,%2,%3}, {%4,%5,%6,%7}, {%8,%9}, {%0,%1,%2,%3};"
                 : "+f"(c[0]), "+f"(c[1]), "+f"(c[2]), "+f"(c[3])
                 : "r"(a[0]), "r"(a[1]), "r"(a[2]), "r"(a[3]), "r"(b[0]), "r"(b[1]));
}

// swizzled byte offset within a 128x32-float tile (rows of 128 bytes)
__device__ __forceinline__ uint32_t swz(int row, uint32_t bytecol) {
    return (uint32_t)row * 128u + (bytecol ^ (((uint32_t)row & 7u) << 4));
}

__device__ __forceinline__ void load_tile_async(const float* __restrict__ src, int ld,
                                                int k0, uint32_t dst, int tid) {
    #pragma unroll
    for (int i = 0; i < 4; ++i) {
        int idx = i * 256 + tid;
        int r = idx >> 3, f = idx & 7;
        cp_async16(dst + swz(r, (uint32_t)(f * 16)), src + (size_t)r * ld + k0 + f * 4);
    }
}

// ============ TF32 HMMA GEMM, 3-stage pipeline ============
// EPI: 0 fp32 out; 1 gelu -> tf32-rounded; 2 +R residual
#define MM_SMEM_BYTES 98304
template <int EPI>
__global__ void __launch_bounds__(256) mm_kernel(const float* __restrict__ A,
                                                 const float* __restrict__ Bt,
                                                 const float* __restrict__ bias,
                                                 float* __restrict__ Cout,
                                                 const float* __restrict__ R,
                                                 int M, int N, int K) {
    extern __shared__ char smem[];
    const int tid = threadIdx.x;
    const int wid = tid >> 5, lane = tid & 31;
    const int bx = blockIdx.x, by = blockIdx.y;
    const uint32_t sb = s2u(smem);
    // stages: A at 0/16K/32K, B at 48K/64K/80K
    uint32_t asb[3], bsb[3];
    #pragma unroll
    for (int s = 0; s < 3; ++s) { asb[s] = sb + s * 16384; bsb[s] = sb + 49152 + s * 16384; }

    const float* Abase = A + (size_t)by * 128 * K;
    const float* Bbase = Bt + (size_t)bx * 128 * K;
    const int nk = K >> 5;

    const int warp_m = (wid >> 2) * 64;
    const int warp_n = (wid & 3) * 32;
    const int tg = lane >> 2;
    const int tq = lane & 3;

    float acc[4][4][4];
    #pragma unroll
    for (int i = 0; i < 4; ++i)
        #pragma unroll
        for (int j = 0; j < 4; ++j)
            #pragma unroll
            for (int q = 0; q < 4; ++q) acc[i][j][q] = 0.f;

    // prologue: stages 0 and 1
    load_tile_async(Abase, K, 0, asb[0], tid);
    load_tile_async(Bbase, K, 0, bsb[0], tid);
    cp_commit();
    if (nk > 1) {
        load_tile_async(Abase, K, 32, asb[1], tid);
        load_tile_async(Bbase, K, 32, bsb[1], tid);
    }
    cp_commit();

    for (int c = 0; c < nk; ++c) {
        if (c == nk - 1) cp_wait<0>(); else cp_wait<1>();
        __syncthreads();
        const int cur = c % 3;
        const uint32_t aoff = asb[cur] - sb;
        const uint32_t boff = bsb[cur] - sb;

        #pragma unroll
        for (int ks = 0; ks < 4; ++ks) {
            const uint32_t c0 = (uint32_t)((ks * 8 + tq) * 4);
            uint32_t a[4][4];
            #pragma unroll
            for (int mt = 0; mt < 4; ++mt) {
                int r0 = warp_m + mt * 16 + tg;
                int r1 = r0 + 8;
                a[mt][0] = *(const uint32_t*)(smem + aoff + swz(r0, c0));
                a[mt][1] = *(const uint32_t*)(smem + aoff + swz(r1, c0));
                a[mt][2] = *(const uint32_t*)(smem + aoff + swz(r0, c0 + 16));
                a[mt][3] = *(const uint32_t*)(smem + aoff + swz(r1, c0 + 16));
            }
            uint32_t b[4][2];
            #pragma unroll
            for (int nt = 0; nt < 4; ++nt) {
                int nr = warp_n + nt * 8 + tg;
                b[nt][0] = *(const uint32_t*)(smem + boff + swz(nr, c0));
                b[nt][1] = *(const uint32_t*)(smem + boff + swz(nr, c0 + 16));
            }
            #pragma unroll
            for (int mt = 0; mt < 4; ++mt)
                #pragma unroll
                for (int nt = 0; nt < 4; ++nt)
                    mma_tf32(acc[mt][nt], a[mt], b[nt]);
        }
        // prefetch stage c+2 (safe: its buffer was consumed in iter c-1)
        if (c + 2 < nk) {
            int ns = (c + 2) % 3;
            load_tile_async(Abase, K, (c + 2) * 32, asb[ns], tid);
            load_tile_async(Bbase, K, (c + 2) * 32, bsb[ns], tid);
        }
        cp_commit();
    }

    // ---- epilogue ----
    const int erow = lane >> 2;
    const int ecol = (lane & 3) * 2;
    #pragma unroll
    for (int nt = 0; nt < 4; ++nt) {
        int gcol = bx * 128 + warp_n + nt * 8 + ecol;
        float b0 = bias[gcol], b1 = bias[gcol + 1];
        #pragma unroll
        for (int mt = 0; mt < 4; ++mt) {
            #pragma unroll
            for (int h = 0; h < 2; ++h) {
                int grow = by * 128 + warp_m + mt * 16 + erow + h * 8;
                if (grow >= M) continue;
                float v0 = acc[mt][nt][h * 2 + 0] + b0;
                float v1 = acc[mt][nt][h * 2 + 1] + b1;
                if (EPI == 1) {
                    v0 = 0.5f * v0 * (1.f + erff(v0 * 0.70710678118654752f));
                    v1 = 0.5f * v1 * (1.f + erff(v1 * 0.70710678118654752f));
                    v0 = tf32r(v0);
                    v1 = tf32r(v1);
                } else if (EPI == 2) {
                    float2 r2 = *reinterpret_cast<const float2*>(R + (size_t)grow * N + gcol);
                    v0 += r2.x; v1 += r2.y;
                }
                float2 o = make_float2(v0, v1);
                *reinterpret_cast<float2*>(Cout + (size_t)grow * N + gcol) = o;
            }
        }
    }
}

// ---------------- weight transpose + tf32 rounding ----------------
__global__ void wt_kernel(const float* __restrict__ W, float* __restrict__ Wt, int K, int N) {
    int idx = blockIdx.x * 256 + threadIdx.x;
    if (idx >= K * N) return;
    int k = idx / N, n = idx % N;
    Wt[(size_t)n * K + k] = tf32r(W[idx]);
}

// ---------------- expanded attention bias ----------------
__global__ void bias_expand_kernel(const float* __restrict__ attn_bias,
                                   const int* __restrict__ bias_idxs) {
    int idx = blockIdx.x * 256 + threadIdx.x;
    if (idx >= NH * NTOK * NTOK) return;
    int h = idx / (NTOK * NTOK), i = idx % (NTOK * NTOK);
    g_biasf[idx] = attn_bias[h * NTOK + bias_idxs[i]];
}

// ---------------- block reduce (128 threads) ----------------
__device__ __forceinline__ void blockReduce2_128(float& a, float& b) {
    __shared__ float sa[4], sb_[4];
    int lane = threadIdx.x & 31, wid = threadIdx.x >> 5;
    #pragma unroll
    for (int o = 16; o > 0; o >>= 1) {
        a += __shfl_down_sync(0xffffffffu, a, o);
        b += __shfl_down_sync(0xffffffffu, b, o);
    }
    if (lane == 0) { sa[wid] = a; sb_[wid] = b; }
    __syncthreads();
    if (threadIdx.x == 0) {
        a = sa[0] + sa[1] + sa[2] + sa[3];
        b = sb_[0] + sb_[1] + sb_[2] + sb_[3];
        sa[0] = a; sb_[0] = b;
    }
    __syncthreads();
    a = sa[0]; b = sb_[0];
    __syncthreads();
}

// ---------------- LN1 + window partition ----------------
__global__ void ln1_window_kernel(const float* __restrict__ x,
                                  const float* __restrict__ w,
                                  const float* __restrict__ b) {
    int g = blockIdx.x;
    int win = g / NTOK, t = g % NTOK;
    int bb = win / 25, wrem = win % 25;
    int wh = wrem / 5, wwi = wrem % 5;
    int i = t / WS, j = t % WS;
    int row = wh * WS + i, col = wwi * WS + j;
    bool valid = (row < HH) && (col < WW_);
    const float* xp = x + ((size_t)bb * L + row * WW_ + col) * DIM;
    int tid = threadIdx.x;
    float vals[3];
    float s = 0.f, sq = 0.f;
    #pragma unroll
    for (int c = 0; c < 3; ++c) {
        float v = valid ? xp[tid + c * 128] : 0.f;
        vals[c] = v; s += v; sq += v * v;
    }
    blockReduce2_128(s, sq);
    float mu = s * (1.f / DIM);
    float var = sq * (1.f / DIM) - mu * mu;
    float inv = rsqrtf(var + EPSV);
    float* op = g_xn + (size_t)g * DIM;
    #pragma unroll
    for (int c = 0; c < 3; ++c) {
        int idx = tid + c * 128;
        op[idx] = tf32r((vals[c] - mu) * inv * w[idx] + b[idx]);
    }
}

// ---------------- LN2 ----------------
__global__ void ln2_kernel(const float* __restrict__ w,
                           const float* __restrict__ b) {
    int g = blockIdx.x;
    const float* xp = g_xb + (size_t)g * DIM;
    int tid = threadIdx.x;
    float vals[3];
    float s = 0.f, sq = 0.f;
    #pragma unroll
    for (int c = 0; c < 3; ++c) {
        float v = xp[tid + c * 128];
        vals[c] = v; s += v; sq += v * v;
    }
    blockReduce2_128(s, sq);
    float mu = s * (1.f / DIM);
    float var = sq * (1.f / DIM) - mu * mu;
    float inv = rsqrtf(var + EPSV);
    float* op = g_xn2 + (size_t)g * DIM;
    #pragma unroll
    for (int c = 0; c < 3; ++c) {
        int idx = tid + c * 128;
        op[idx] = tf32r((vals[c] - mu) * inv * w[idx] + b[idx]);
    }
}

// ---------------- fused windowed attention ----------------
__global__ void attn_kernel() {
    int w = blockIdx.x;
    int h = blockIdx.y;
    __shared__ float q[NTOK * HD];
    __shared__ float k[NTOK * HD];
    __shared__ float v[NTOK * HD];
    __shared__ float s[NTOK * 50];
    int tid = threadIdx.x;
    int wid = tid >> 5, lane = tid & 31;
    const float* base = g_qkv + (size_t)w * NTOK * (3 * DIM);
    for (int i = tid; i < NTOK * HD; i += 256) {
        int t = i / HD, d = i % HD;
        const float* p = base + (size_t)t * (3 * DIM) + h * 96 + d;
        q[i] = p[0];
        k[i] = p[32];
        v[i] = p[64];
    }
    __syncthreads();
    const float scale = 0.1767766952966369f;
    const float* bf = g_biasf + (size_t)h * NTOK * NTOK;
    for (int i = tid; i < NTOK * NTOK; i += 256) {
        int n = i / NTOK, m = i % NTOK;
        float acc = 0.f;
        #pragma unroll
        for (int d = 0; d < HD; ++d) acc += q[n * HD + d] * k[m * HD + d];
        s[n * 50 + m] = acc * scale + bf[i];
    }
    __syncthreads();
    // warp-parallel softmax: each warp owns rows wid, wid+8, ...
    for (int r = wid; r < NTOK; r += 8) {
        float v0 = (lane < NTOK) ? s[r * 50 + lane] : -1e30f;
        float v1 = (lane + 32 < NTOK) ? s[r * 50 + lane + 32] : -1e30f;
        float mx = fmaxf(v0, v1);
        #pragma unroll
        for (int o = 16; o > 0; o >>= 1) mx = fmaxf(mx, __shfl_xor_sync(0xffffffffu, mx, o));
        float e0 = (lane < NTOK) ? expf(v0 - mx) : 0.f;
        float e1 = (lane + 32 < NTOK) ? expf(v1 - mx) : 0.f;
        float sum = e0 + e1;
        #pragma unroll
        for (int o = 16; o > 0; o >>= 1) sum += __shfl_xor_sync(0xffffffffu, sum, o);
        float inv = 1.f / sum;
        if (lane < NTOK) s[r * 50 + lane] = e0 * inv;
        if (lane + 32 < NTOK) s[r * 50 + lane + 32] = e1 * inv;
    }
    __syncthreads();
    for (int i = tid; i < NTOK * HD; i += 256) {
        int n = i / HD, d = i % HD;
        float acc = 0.f;
        #pragma unroll 7
        for (int m = 0; m < NTOK; ++m) acc += s[n * 50 + m] * v[m * HD + d];
        g_ao[((size_t)w * NTOK + n) * DIM + h * HD + d] = tf32r(acc);
    }
}

// ---------------- un-window + residual add ----------------
__global__ void scatter_kernel(const float* __restrict__ x) {
    size_t idx = (size_t)blockIdx.x * blockDim.x + threadIdx.x;
    size_t total = (size_t)BL * (DIM / 4);
    if (idx >= total) return;
    int c4 = idx % (DIM / 4);
    size_t l_ = idx / (DIM / 4);
    int l = (int)(l_ % L);
    int bb = (int)(l_ / L);
    int row = l / WW_, col = l % WW_;
    int win = bb * 25 + (row / WS) * 5 + (col / WS);
    int t = (row % WS) * WS + (col % WS);
    float4 pv = *reinterpret_cast<const float4*>(
        g_proj + ((size_t)win * NTOK + t) * DIM + c4 * 4);
    float4 xv = *reinterpret_cast<const float4*>(x + idx * 4);
    pv.x += xv.x; pv.y += xv.y; pv.z += xv.z; pv.w += xv.w;
    *reinterpret_cast<float4*>(g_xa + idx * 4) = pv;
}

// ---------------- depthwise 3x3 conv + BN ----------------
__global__ void conv_bn_kernel(const float* __restrict__ cw,
                               const float* __restrict__ bg,
                               const float* __restrict__ bb_,
                               const float* __restrict__ bm,
                               const float* __restrict__ bv) {
    size_t idx = (size_t)blockIdx.x * blockDim.x + threadIdx.x;
    size_t total = (size_t)BL * DIM;
    if (idx >= total) return;
    int c = idx % DIM;
    size_t l_ = idx / DIM;
    int l = (int)(l_ % L);
    int bb = (int)(l_ / L);
    int row = l / WW_, col = l % WW_;
    float acc = 0.f;
    #pragma unroll
    for (int dh = -1; dh <= 1; ++dh) {
        #pragma unroll
        for (int dw = -1; dw <= 1; ++dw) {
            int r = row + dh, cc = col + dw;
            if (r >= 0 && r < HH && cc >= 0 && cc < WW_) {
                acc += g_xa[((size_t)bb * L + r * WW_ + cc) * DIM + c] *
                       cw[c * 9 + (dh + 1) * 3 + (dw + 1)];
            }
        }
    }
    float inv = rsqrtf(bv[c] + EPSV);
    g_xb[idx] = (acc - bm[c]) * inv * bg[c] + bb_[c];
}

// ---------------- launch ----------------
extern "C" void kernel_launch(void* const* d_in, const int* in_sizes, int n_in,
                              void* d_out, int out_size) {
    const float* x         = (const float*)d_in[0];
    const float* ln1_w     = (const float*)d_in[1];
    const float* ln1_b     = (const float*)d_in[2];
    const float* qkv_w     = (const float*)d_in[3];
    const float* qkv_b     = (const float*)d_in[4];
    const float* proj_w    = (const float*)d_in[5];
    const float* proj_b    = (const float*)d_in[6];
    const float* attn_bias = (const float*)d_in[7];
    const int*   bias_idxs = (const int*)d_in[8];
    const float* conv_w    = (const float*)d_in[9];
    const float* bn_g      = (const float*)d_in[10];
    const float* bn_b      = (const float*)d_in[11];
    const float* bn_m      = (const float*)d_in[12];
    const float* bn_v      = (const float*)d_in[13];
    const float* ln2_w     = (const float*)d_in[14];
    const float* ln2_b     = (const float*)d_in[15];
    const float* fc1_w     = (const float*)d_in[16];
    const float* fc1_b     = (const float*)d_in[17];
    const float* fc2_w     = (const float*)d_in[18];
    const float* fc2_b     = (const float*)d_in[19];
    float* out = (float*)d_out;

    float *xn, *qkv, *ao, *pj, *xb, *xn2, *hbuf, *wq, *wp, *w1, *w2;
    cudaGetSymbolAddress((void**)&xn,  g_xn);
    cudaGetSymbolAddress((void**)&qkv, g_qkv);
    cudaGetSymbolAddress((void**)&ao,  g_ao);
    cudaGetSymbolAddress((void**)&pj,  g_proj);
    cudaGetSymbolAddress((void**)&xb,  g_xb);
    cudaGetSymbolAddress((void**)&xn2, g_xn2);
    cudaGetSymbolAddress((void**)&hbuf, g_h);
    cudaGetSymbolAddress((void**)&wq,  g_wq);
    cudaGetSymbolAddress((void**)&wp,  g_wp);
    cudaGetSymbolAddress((void**)&w1,  g_w1);
    cudaGetSymbolAddress((void**)&w2,  g_w2);

    cudaFuncSetAttribute(mm_kernel<0>, cudaFuncAttributeMaxDynamicSharedMemorySize, MM_SMEM_BYTES);
    cudaFuncSetAttribute(mm_kernel<1>, cudaFuncAttributeMaxDynamicSharedMemorySize, MM_SMEM_BYTES);
    cudaFuncSetAttribute(mm_kernel<2>, cudaFuncAttributeMaxDynamicSharedMemorySize, MM_SMEM_BYTES);

    // 0) weight prep + bias expansion
    wt_kernel<<<(DIM * 3 * DIM + 255) / 256, 256>>>(qkv_w, wq, DIM, 3 * DIM);
    wt_kernel<<<(DIM * DIM + 255) / 256, 256>>>(proj_w, wp, DIM, DIM);
    wt_kernel<<<(DIM * FFN + 255) / 256, 256>>>(fc1_w, w1, DIM, FFN);
    wt_kernel<<<(FFN * DIM + 255) / 256, 256>>>(fc2_w, w2, FFN, DIM);
    bias_expand_kernel<<<(NH * NTOK * NTOK + 255) / 256, 256>>>(attn_bias, bias_idxs);

    // 1) LN1 + window partition
    ln1_window_kernel<<<TOKENS, 128>>>(x, ln1_w, ln1_b);

    // 2) qkv GEMM
    {
        dim3 grid((3 * DIM) / 128, MPAD / 128);
        mm_kernel<0><<<grid, 256, MM_SMEM_BYTES>>>(xn, wq, qkv_b, qkv, nullptr,
                                                   TOKENS, 3 * DIM, DIM);
    }

    // 3) windowed attention
    {
        dim3 grid(NWIN, NH);
        attn_kernel<<<grid, 256>>>();
    }

    // 4) proj GEMM
    {
        dim3 grid(DIM / 128, MPAD / 128);
        mm_kernel<0><<<grid, 256, MM_SMEM_BYTES>>>(ao, wp, proj_b, pj, nullptr,
                                                   TOKENS, DIM, DIM);
    }

    // 5) un-window + residual
    {
        size_t total = (size_t)BL * (DIM / 4);
        scatter_kernel<<<(unsigned)((total + 255) / 256), 256>>>(x);
    }

    // 6) depthwise conv + BN
    {
        size_t total = (size_t)BL * DIM;
        conv_bn_kernel<<<(unsigned)((total + 255) / 256), 256>>>(conv_w, bn_g, bn_b, bn_m, bn_v);
    }

    // 7) LN2
    ln2_kernel<<<BL, 128>>>(ln2_w, ln2_b);

    // 8) fc1 + gelu
    {
        dim3 grid(FFN / 128, BL / 128);
        mm_kernel<1><<<grid, 256, MM_SMEM_BYTES>>>(xn2, w1, fc1_b, hbuf, nullptr,
                                                   BL, FFN, DIM);
    }

    // 9) fc2 + residual -> out
    {
        dim3 grid(DIM / 128, BL / 128);
        mm_kernel<2><<<grid, 256, MM_SMEM_BYTES>>>(hbuf, w2, fc2_b, out, xb,
                                                   BL, DIM, FFN);
    }
}

// round 6
// speedup vs baseline: 2.3600x; 1.0730x over previous
#include <cuda_runtime.h>
#include <cuda_fp16.h>
#include <math.h>
#include <stdint.h>

#define BATCH 32
#define HH 32
#define WW_ 32
#define L 1024
#define DIM 384
#define NH 12
#define HD 32
#define WS 7
#define NWIN 800
#define NTOK 49
#define TOKENS (NWIN * NTOK)   // 39200
#define MPAD 39296
#define BL (BATCH * L)         // 32768
#define FFN (4 * DIM)          // 1536
#define EPSV 1e-5f

// ---------------- scratch ----------------
__device__ __half g_xn[(size_t)MPAD * DIM];        // LN1 out, fp16
__device__ __half g_qkv[(size_t)MPAD * 3 * DIM];   // qkv, fp16
__device__ __half g_ao[(size_t)MPAD * DIM];        // attn out, fp16
__device__ float  g_xa[(size_t)BL * DIM];          // x + proj (scattered)
__device__ float  g_xb[(size_t)BL * DIM];          // after conv+BN
__device__ float  g_xn2[(size_t)BL * DIM];         // LN2 out (tf32-rounded)
__device__ float  g_h[(size_t)BL * FFN];           // fc1+gelu out
__device__ __half g_wqh[(size_t)3 * DIM * DIM];    // fp16 transposed weights
__device__ __half g_wph[(size_t)DIM * DIM];
__device__ float  g_w1[(size_t)FFN * DIM];         // tf32 transposed weights
__device__ float  g_w2[(size_t)DIM * FFN];
__device__ float  g_biasf[(size_t)NH * NTOK * NTOK];

// ================= common helpers =================
__device__ __forceinline__ uint32_t s2u(const void* p) {
    uint32_t a;
    asm("{ .reg .u64 t; cvta.to.shared.u64 t, %1; cvt.u32.u64 %0, t; }" : "=r"(a) : "l"(p));
    return a;
}
__device__ __forceinline__ float tf32r(float x) {
    float y;
    asm("cvt.rna.tf32.f32 %0, %1;" : "=f"(y) : "f"(x));
    return y;
}
__device__ __forceinline__ void cp_async16(uint32_t dst, const void* src) {
    asm volatile("cp.async.cg.shared.global [%0], [%1], 16;" :: "r"(dst), "l"(src) : "memory");
}
__device__ __forceinline__ void cp_commit() {
    asm volatile("cp.async.commit_group;" ::: "memory");
}
template <int N>
__device__ __forceinline__ void cp_wait() {
    asm volatile("cp.async.wait_group %0;" :: "n"(N) : "memory");
}

// ======================================================================
//                       FP16 GEMM (qkv / proj)
// ======================================================================
__device__ __forceinline__ uint32_t sw128(uint32_t byte_off) {
    return byte_off ^ ((byte_off >> 3) & 0x70u);
}
__device__ __forceinline__ void ldsm_x4(uint32_t* r, uint32_t addr) {
    asm volatile("ldmatrix.sync.aligned.m8n8.x4.shared.b16 {%0,%1,%2,%3}, [%4];"
                 : "=r"(r[0]), "=r"(r[1]), "=r"(r[2]), "=r"(r[3]) : "r"(addr));
}
__device__ __forceinline__ void mma_f16(float* c, const uint32_t* a, const uint32_t* b) {
    asm volatile("mma.sync.aligned.m16n8k16.row.col.f32.f16.f16.f32 "
                 "{%0,%1,%2,%3}, {%4,%5,%6,%7}, {%8,%9}, {%0,%1,%2,%3};"
                 : "+f"(c[0]), "+f"(c[1]), "+f"(c[2]), "+f"(c[3])
                 : "r"(a[0]), "r"(a[1]), "r"(a[2]), "r"(a[3]), "r"(b[0]), "r"(b[1]));
}
// load one 128x64 fp16 tile (row-major) into SW128-swizzled smem
__device__ __forceinline__ void load_tile_h(const __half* __restrict__ src, int ld,
                                            int k0, uint32_t dst, int tid) {
    #pragma unroll
    for (int i = 0; i < 4; ++i) {
        int idx = i * 256 + tid;
        int r = idx >> 3, f = idx & 7;
        cp_async16(dst + sw128((uint32_t)(r * 128 + f * 16)),
                   src + (size_t)r * ld + k0 + f * 8);
    }
}

// EPI: 0 -> fp16 out + bias;  1 -> scatter+residual fp32 out (+bias)
#define HMM_SMEM_BYTES 65536
template <int EPI>
__global__ void __launch_bounds__(256) hmm_kernel(const __half* __restrict__ A,
                                                  const __half* __restrict__ Bt,
                                                  const float* __restrict__ bias,
                                                  void* __restrict__ Cout,
                                                  const float* __restrict__ X,
                                                  int M, int N, int K) {
    extern __shared__ char smem[];
    const int tid = threadIdx.x;
    const int wid = tid >> 5, lane = tid & 31;
    const int bx = blockIdx.x, by = blockIdx.y;
    const uint32_t sb = s2u(smem);
    const uint32_t asb[2] = { sb, sb + 16384 };
    const uint32_t bsb[2] = { sb + 32768, sb + 49152 };

    const __half* Abase = A + (size_t)by * 128 * K;
    const __half* Bbase = Bt + (size_t)bx * 128 * K;
    const int nk = K >> 6;

    const int warp_m = (wid >> 2) * 64;
    const int warp_n = (wid & 3) * 32;

    float acc[4][4][4];
    #pragma unroll
    for (int i = 0; i < 4; ++i)
        #pragma unroll
        for (int j = 0; j < 4; ++j)
            #pragma unroll
            for (int q = 0; q < 4; ++q) acc[i][j][q] = 0.f;

    load_tile_h(Abase, K, 0, asb[0], tid);
    load_tile_h(Bbase, K, 0, bsb[0], tid);
    cp_commit();

    const int a_row = (lane & 7) + ((lane >> 3) & 1) * 8;
    const int a_kc  = (lane >> 4) * 8;
    const int b_nr  = (lane & 7) + ((lane >> 4) * 8);
    const int b_kc  = ((lane >> 3) & 1) * 8;

    for (int c = 0; c < nk; ++c) {
        int cur = c & 1;
        if (c + 1 < nk) {
            load_tile_h(Abase, K, (c + 1) * 64, asb[cur ^ 1], tid);
            load_tile_h(Bbase, K, (c + 1) * 64, bsb[cur ^ 1], tid);
            cp_commit();
            cp_wait<1>();
        } else {
            cp_wait<0>();
        }
        __syncthreads();

        #pragma unroll
        for (int ks = 0; ks < 4; ++ks) {
            uint32_t a[4][4];
            #pragma unroll
            for (int mt = 0; mt < 4; ++mt) {
                int row = warp_m + mt * 16 + a_row;
                int kc = ks * 16 + a_kc;
                ldsm_x4(a[mt], asb[cur] + sw128((uint32_t)(row * 128 + kc * 2)));
            }
            uint32_t b[4][2];
            #pragma unroll
            for (int np = 0; np < 2; ++np) {
                uint32_t r4[4];
                int nrow = warp_n + np * 16 + b_nr;
                int kc = ks * 16 + b_kc;
                ldsm_x4(r4, bsb[cur] + sw128((uint32_t)(nrow * 128 + kc * 2)));
                b[np * 2 + 0][0] = r4[0]; b[np * 2 + 0][1] = r4[1];
                b[np * 2 + 1][0] = r4[2]; b[np * 2 + 1][1] = r4[3];
            }
            #pragma unroll
            for (int mt = 0; mt < 4; ++mt)
                #pragma unroll
                for (int nt = 0; nt < 4; ++nt)
                    mma_f16(acc[mt][nt], a[mt], b[nt]);
        }
        __syncthreads();
    }

    const int erow = lane >> 2;
    const int ecol = (lane & 3) * 2;
    #pragma unroll
    for (int nt = 0; nt < 4; ++nt) {
        int gcol = bx * 128 + warp_n + nt * 8 + ecol;
        float b0 = bias[gcol], b1 = bias[gcol + 1];
        #pragma unroll
        for (int mt = 0; mt < 4; ++mt) {
            #pragma unroll
            for (int h = 0; h < 2; ++h) {
                int grow = by * 128 + warp_m + mt * 16 + erow + h * 8;
                if (grow >= M) continue;
                float v0 = acc[mt][nt][h * 2 + 0] + b0;
                float v1 = acc[mt][nt][h * 2 + 1] + b1;
                if (EPI == 0) {
                    __half2 hp = __floats2half2_rn(v0, v1);
                    *reinterpret_cast<__half2*>((__half*)Cout + (size_t)grow * N + gcol) = hp;
                } else {
                    // scatter: window row -> (b, l) with validity check
                    int win = grow / NTOK, t = grow % NTOK;
                    int bb = win / 25, wrem = win % 25;
                    int r = (wrem / 5) * WS + t / WS;
                    int cc = (wrem % 5) * WS + t % WS;
                    if (r < HH && cc < WW_) {
                        size_t base = ((size_t)bb * L + r * WW_ + cc) * DIM + gcol;
                        float2 xv = *reinterpret_cast<const float2*>(X + base);
                        float2 o = make_float2(v0 + xv.x, v1 + xv.y);
                        *reinterpret_cast<float2*>((float*)Cout + base) = o;
                    }
                }
            }
        }
    }
}

// ======================================================================
//                      TF32 GEMM (fc1 / fc2)
// ======================================================================
__device__ __forceinline__ void mma_tf32(float* c, const uint32_t* a, const uint32_t* b) {
    asm volatile("mma.sync.aligned.m16n8k8.row.col.f32.tf32.tf32.f32 "
                 "{%0,%1,%2,%3}, {%4,%5,%6,%7}, {%8,%9}, {%0,%1,%2,%3};"
                 : "+f"(c[0]), "+f"(c[1]), "+f"(c[2]), "+f"(c[3])
                 : "r"(a[0]), "r"(a[1]), "r"(a[2]), "r"(a[3]), "r"(b[0]), "r"(b[1]));
}
__device__ __forceinline__ uint32_t swz(int row, uint32_t bytecol) {
    return (uint32_t)row * 128u + (bytecol ^ (((uint32_t)row & 7u) << 4));
}
__device__ __forceinline__ void load_tile_f(const float* __restrict__ src, int ld,
                                            int k0, uint32_t dst, int tid) {
    #pragma unroll
    for (int i = 0; i < 4; ++i) {
        int idx = i * 256 + tid;
        int r = idx >> 3, f = idx & 7;
        cp_async16(dst + swz(r, (uint32_t)(f * 16)), src + (size_t)r * ld + k0 + f * 4);
    }
}

// EPI: 1 gelu -> tf32-rounded; 2 +R residual
#define MM_SMEM_BYTES 98304
template <int EPI>
__global__ void __launch_bounds__(256) mm_kernel(const float* __restrict__ A,
                                                 const float* __restrict__ Bt,
                                                 const float* __restrict__ bias,
                                                 float* __restrict__ Cout,
                                                 const float* __restrict__ R,
                                                 int M, int N, int K) {
    extern __shared__ char smem[];
    const int tid = threadIdx.x;
    const int wid = tid >> 5, lane = tid & 31;
    const int bx = blockIdx.x, by = blockIdx.y;
    const uint32_t sb = s2u(smem);
    uint32_t asb[3], bsb[3];
    #pragma unroll
    for (int s = 0; s < 3; ++s) { asb[s] = sb + s * 16384; bsb[s] = sb + 49152 + s * 16384; }

    const float* Abase = A + (size_t)by * 128 * K;
    const float* Bbase = Bt + (size_t)bx * 128 * K;
    const int nk = K >> 5;

    const int warp_m = (wid >> 2) * 64;
    const int warp_n = (wid & 3) * 32;
    const int tg = lane >> 2;
    const int tq = lane & 3;

    float acc[4][4][4];
    #pragma unroll
    for (int i = 0; i < 4; ++i)
        #pragma unroll
        for (int j = 0; j < 4; ++j)
            #pragma unroll
            for (int q = 0; q < 4; ++q) acc[i][j][q] = 0.f;

    load_tile_f(Abase, K, 0, asb[0], tid);
    load_tile_f(Bbase, K, 0, bsb[0], tid);
    cp_commit();
    if (nk > 1) {
        load_tile_f(Abase, K, 32, asb[1], tid);
        load_tile_f(Bbase, K, 32, bsb[1], tid);
    }
    cp_commit();

    for (int c = 0; c < nk; ++c) {
        if (c == nk - 1) cp_wait<0>(); else cp_wait<1>();
        __syncthreads();
        const int cur = c % 3;
        const uint32_t aoff = asb[cur] - sb;
        const uint32_t boff = bsb[cur] - sb;

        #pragma unroll
        for (int ks = 0; ks < 4; ++ks) {
            const uint32_t c0 = (uint32_t)((ks * 8 + tq) * 4);
            uint32_t a[4][4];
            #pragma unroll
            for (int mt = 0; mt < 4; ++mt) {
                int r0 = warp_m + mt * 16 + tg;
                int r1 = r0 + 8;
                a[mt][0] = *(const uint32_t*)(smem + aoff + swz(r0, c0));
                a[mt][1] = *(const uint32_t*)(smem + aoff + swz(r1, c0));
                a[mt][2] = *(const uint32_t*)(smem + aoff + swz(r0, c0 + 16));
                a[mt][3] = *(const uint32_t*)(smem + aoff + swz(r1, c0 + 16));
            }
            uint32_t b[4][2];
            #pragma unroll
            for (int nt = 0; nt < 4; ++nt) {
                int nr = warp_n + nt * 8 + tg;
                b[nt][0] = *(const uint32_t*)(smem + boff + swz(nr, c0));
                b[nt][1] = *(const uint32_t*)(smem + boff + swz(nr, c0 + 16));
            }
            #pragma unroll
            for (int mt = 0; mt < 4; ++mt)
                #pragma unroll
                for (int nt = 0; nt < 4; ++nt)
                    mma_tf32(acc[mt][nt], a[mt], b[nt]);
        }
        if (c + 2 < nk) {
            int ns = (c + 2) % 3;
            load_tile_f(Abase, K, (c + 2) * 32, asb[ns], tid);
            load_tile_f(Bbase, K, (c + 2) * 32, bsb[ns], tid);
        }
        cp_commit();
    }

    const int erow = lane >> 2;
    const int ecol = (lane & 3) * 2;
    #pragma unroll
    for (int nt = 0; nt < 4; ++nt) {
        int gcol = bx * 128 + warp_n + nt * 8 + ecol;
        float b0 = bias[gcol], b1 = bias[gcol + 1];
        #pragma unroll
        for (int mt = 0; mt < 4; ++mt) {
            #pragma unroll
            for (int h = 0; h < 2; ++h) {
                int grow = by * 128 + warp_m + mt * 16 + erow + h * 8;
                if (grow >= M) continue;
                float v0 = acc[mt][nt][h * 2 + 0] + b0;
                float v1 = acc[mt][nt][h * 2 + 1] + b1;
                if (EPI == 1) {
                    v0 = 0.5f * v0 * (1.f + erff(v0 * 0.70710678118654752f));
                    v1 = 0.5f * v1 * (1.f + erff(v1 * 0.70710678118654752f));
                    v0 = tf32r(v0);
                    v1 = tf32r(v1);
                } else if (EPI == 2) {
                    float2 r2 = *reinterpret_cast<const float2*>(R + (size_t)grow * N + gcol);
                    v0 += r2.x; v1 += r2.y;
                }
                float2 o = make_float2(v0, v1);
                *reinterpret_cast<float2*>(Cout + (size_t)grow * N + gcol) = o;
            }
        }
    }
}

// ---------------- weight prep ----------------
__global__ void wt_f_kernel(const float* __restrict__ W, float* __restrict__ Wt, int K, int N) {
    int idx = blockIdx.x * 256 + threadIdx.x;
    if (idx >= K * N) return;
    int k = idx / N, n = idx % N;
    Wt[(size_t)n * K + k] = tf32r(W[idx]);
}
__global__ void wt_h_kernel(const float* __restrict__ W, __half* __restrict__ Wt, int K, int N) {
    int idx = blockIdx.x * 256 + threadIdx.x;
    if (idx >= K * N) return;
    int k = idx / N, n = idx % N;
    Wt[(size_t)n * K + k] = __float2half(W[idx]);
}
__global__ void bias_expand_kernel(const float* __restrict__ attn_bias,
                                   const int* __restrict__ bias_idxs) {
    int idx = blockIdx.x * 256 + threadIdx.x;
    if (idx >= NH * NTOK * NTOK) return;
    int h = idx / (NTOK * NTOK), i = idx % (NTOK * NTOK);
    g_biasf[idx] = attn_bias[h * NTOK + bias_idxs[i]];
}

// ---------------- block reduce ----------------
__device__ __forceinline__ void blockReduce2_128(float& a, float& b) {
    __shared__ float sa[4], sb_[4];
    int lane = threadIdx.x & 31, wid = threadIdx.x >> 5;
    #pragma unroll
    for (int o = 16; o > 0; o >>= 1) {
        a += __shfl_down_sync(0xffffffffu, a, o);
        b += __shfl_down_sync(0xffffffffu, b, o);
    }
    if (lane == 0) { sa[wid] = a; sb_[wid] = b; }
    __syncthreads();
    if (threadIdx.x == 0) {
        a = sa[0] + sa[1] + sa[2] + sa[3];
        b = sb_[0] + sb_[1] + sb_[2] + sb_[3];
        sa[0] = a; sb_[0] = b;
    }
    __syncthreads();
    a = sa[0]; b = sb_[0];
    __syncthreads();
}

// ---------------- LN1 + window partition -> fp16 ----------------
__global__ void ln1_window_kernel(const float* __restrict__ x,
                                  const float* __restrict__ w,
                                  const float* __restrict__ b) {
    int g = blockIdx.x;
    int win = g / NTOK, t = g % NTOK;
    int bb = win / 25, wrem = win % 25;
    int wh = wrem / 5, wwi = wrem % 5;
    int i = t / WS, j = t % WS;
    int row = wh * WS + i, col = wwi * WS + j;
    bool valid = (row < HH) && (col < WW_);
    const float* xp = x + ((size_t)bb * L + row * WW_ + col) * DIM;
    int tid = threadIdx.x;
    float vals[3];
    float s = 0.f, sq = 0.f;
    #pragma unroll
    for (int c = 0; c < 3; ++c) {
        float v = valid ? xp[tid + c * 128] : 0.f;
        vals[c] = v; s += v; sq += v * v;
    }
    blockReduce2_128(s, sq);
    float mu = s * (1.f / DIM);
    float var = sq * (1.f / DIM) - mu * mu;
    float inv = rsqrtf(var + EPSV);
    __half* op = g_xn + (size_t)g * DIM;
    #pragma unroll
    for (int c = 0; c < 3; ++c) {
        int idx = tid + c * 128;
        op[idx] = __float2half((vals[c] - mu) * inv * w[idx] + b[idx]);
    }
}

// ---------------- LN2 -> tf32-rounded fp32 ----------------
__global__ void ln2_kernel(const float* __restrict__ w,
                           const float* __restrict__ b) {
    int g = blockIdx.x;
    const float* xp = g_xb + (size_t)g * DIM;
    int tid = threadIdx.x;
    float vals[3];
    float s = 0.f, sq = 0.f;
    #pragma unroll
    for (int c = 0; c < 3; ++c) {
        float v = xp[tid + c * 128];
        vals[c] = v; s += v; sq += v * v;
    }
    blockReduce2_128(s, sq);
    float mu = s * (1.f / DIM);
    float var = sq * (1.f / DIM) - mu * mu;
    float inv = rsqrtf(var + EPSV);
    float* op = g_xn2 + (size_t)g * DIM;
    #pragma unroll
    for (int c = 0; c < 3; ++c) {
        int idx = tid + c * 128;
        op[idx] = tf32r((vals[c] - mu) * inv * w[idx] + b[idx]);
    }
}

// ---------------- fused windowed attention (fp16 qkv) ----------------
__global__ void attn_kernel() {
    int w = blockIdx.x;
    int h = blockIdx.y;
    __shared__ float q[NTOK * HD];
    __shared__ float k[NTOK * HD];
    __shared__ float v[NTOK * HD];
    __shared__ float s[NTOK * 50];
    int tid = threadIdx.x;
    int wid = tid >> 5, lane = tid & 31;
    const __half* base = g_qkv + (size_t)w * NTOK * (3 * DIM);
    for (int i = tid; i < NTOK * HD; i += 256) {
        int t = i / HD, d = i % HD;
        const __half* p = base + (size_t)t * (3 * DIM) + h * 96 + d;
        q[i] = __half2float(p[0]);
        k[i] = __half2float(p[32]);
        v[i] = __half2float(p[64]);
    }
    __syncthreads();
    const float scale = 0.1767766952966369f;
    const float* bf = g_biasf + (size_t)h * NTOK * NTOK;
    for (int i = tid; i < NTOK * NTOK; i += 256) {
        int n = i / NTOK, m = i % NTOK;
        float acc = 0.f;
        #pragma unroll
        for (int d = 0; d < HD; ++d) acc += q[n * HD + d] * k[m * HD + d];
        s[n * 50 + m] = acc * scale + bf[i];
    }
    __syncthreads();
    for (int r = wid; r < NTOK; r += 8) {
        float v0 = (lane < NTOK) ? s[r * 50 + lane] : -1e30f;
        float v1 = (lane + 32 < NTOK) ? s[r * 50 + lane + 32] : -1e30f;
        float mx = fmaxf(v0, v1);
        #pragma unroll
        for (int o = 16; o > 0; o >>= 1) mx = fmaxf(mx, __shfl_xor_sync(0xffffffffu, mx, o));
        float e0 = (lane < NTOK) ? expf(v0 - mx) : 0.f;
        float e1 = (lane + 32 < NTOK) ? expf(v1 - mx) : 0.f;
        float sum = e0 + e1;
        #pragma unroll
        for (int o = 16; o > 0; o >>= 1) sum += __shfl_xor_sync(0xffffffffu, sum, o);
        float inv = 1.f / sum;
        if (lane < NTOK) s[r * 50 + lane] = e0 * inv;
        if (lane + 32 < NTOK) s[r * 50 + lane + 32] = e1 * inv;
    }
    __syncthreads();
    for (int i = tid; i < NTOK * HD; i += 256) {
        int n = i / HD, d = i % HD;
        float acc = 0.f;
        #pragma unroll 7
        for (int m = 0; m < NTOK; ++m) acc += s[n * 50 + m] * v[m * HD + d];
        g_ao[((size_t)w * NTOK + n) * DIM + h * HD + d] = __float2half(acc);
    }
}

// ---------------- depthwise 3x3 conv + BN ----------------
__global__ void conv_bn_kernel(const float* __restrict__ cw,
                               const float* __restrict__ bg,
                               const float* __restrict__ bb_,
                               const float* __restrict__ bm,
                               const float* __restrict__ bv) {
    size_t idx = (size_t)blockIdx.x * blockDim.x + threadIdx.x;
    size_t total = (size_t)BL * DIM;
    if (idx >= total) return;
    int c = idx % DIM;
    size_t l_ = idx / DIM;
    int l = (int)(l_ % L);
    int bb = (int)(l_ / L);
    int row = l / WW_, col = l % WW_;
    float acc = 0.f;
    #pragma unroll
    for (int dh = -1; dh <= 1; ++dh) {
        #pragma unroll
        for (int dw = -1; dw <= 1; ++dw) {
            int r = row + dh, cc = col + dw;
            if (r >= 0 && r < HH && cc >= 0 && cc < WW_) {
                acc += g_xa[((size_t)bb * L + r * WW_ + cc) * DIM + c] *
                       cw[c * 9 + (dh + 1) * 3 + (dw + 1)];
            }
        }
    }
    float inv = rsqrtf(bv[c] + EPSV);
    g_xb[idx] = (acc - bm[c]) * inv * bg[c] + bb_[c];
}

// ---------------- launch ----------------
extern "C" void kernel_launch(void* const* d_in, const int* in_sizes, int n_in,
                              void* d_out, int out_size) {
    const float* x         = (const float*)d_in[0];
    const float* ln1_w     = (const float*)d_in[1];
    const float* ln1_b     = (const float*)d_in[2];
    const float* qkv_w     = (const float*)d_in[3];
    const float* qkv_b     = (const float*)d_in[4];
    const float* proj_w    = (const float*)d_in[5];
    const float* proj_b    = (const float*)d_in[6];
    const float* attn_bias = (const float*)d_in[7];
    const int*   bias_idxs = (const int*)d_in[8];
    const float* conv_w    = (const float*)d_in[9];
    const float* bn_g      = (const float*)d_in[10];
    const float* bn_b      = (const float*)d_in[11];
    const float* bn_m      = (const float*)d_in[12];
    const float* bn_v      = (const float*)d_in[13];
    const float* ln2_w     = (const float*)d_in[14];
    const float* ln2_b     = (const float*)d_in[15];
    const float* fc1_w     = (const float*)d_in[16];
    const float* fc1_b     = (const float*)d_in[17];
    const float* fc2_w     = (const float*)d_in[18];
    const float* fc2_b     = (const float*)d_in[19];
    float* out = (float*)d_out;

    __half *xn, *qkv, *ao, *wqh, *wph;
    float *xa, *xb, *xn2, *hbuf, *w1, *w2;
    cudaGetSymbolAddress((void**)&xn,  g_xn);
    cudaGetSymbolAddress((void**)&qkv, g_qkv);
    cudaGetSymbolAddress((void**)&ao,  g_ao);
    cudaGetSymbolAddress((void**)&xa,  g_xa);
    cudaGetSymbolAddress((void**)&xb,  g_xb);
    cudaGetSymbolAddress((void**)&xn2, g_xn2);
    cudaGetSymbolAddress((void**)&hbuf, g_h);
    cudaGetSymbolAddress((void**)&wqh, g_wqh);
    cudaGetSymbolAddress((void**)&wph, g_wph);
    cudaGetSymbolAddress((void**)&w1,  g_w1);
    cudaGetSymbolAddress((void**)&w2,  g_w2);

    cudaFuncSetAttribute(hmm_kernel<0>, cudaFuncAttributeMaxDynamicSharedMemorySize, HMM_SMEM_BYTES);
    cudaFuncSetAttribute(hmm_kernel<1>, cudaFuncAttributeMaxDynamicSharedMemorySize, HMM_SMEM_BYTES);
    cudaFuncSetAttribute(mm_kernel<1>, cudaFuncAttributeMaxDynamicSharedMemorySize, MM_SMEM_BYTES);
    cudaFuncSetAttribute(mm_kernel<2>, cudaFuncAttributeMaxDynamicSharedMemorySize, MM_SMEM_BYTES);

    // 0) weight prep + bias expansion
    wt_h_kernel<<<(DIM * 3 * DIM + 255) / 256, 256>>>(qkv_w, wqh, DIM, 3 * DIM);
    wt_h_kernel<<<(DIM * DIM + 255) / 256, 256>>>(proj_w, wph, DIM, DIM);
    wt_f_kernel<<<(DIM * FFN + 255) / 256, 256>>>(fc1_w, w1, DIM, FFN);
    wt_f_kernel<<<(FFN * DIM + 255) / 256, 256>>>(fc2_w, w2, FFN, DIM);
    bias_expand_kernel<<<(NH * NTOK * NTOK + 255) / 256, 256>>>(attn_bias, bias_idxs);

    // 1) LN1 + window partition (fp16)
    ln1_window_kernel<<<TOKENS, 128>>>(x, ln1_w, ln1_b);

    // 2) qkv GEMM (fp16)
    {
        dim3 grid((3 * DIM) / 128, MPAD / 128);
        hmm_kernel<0><<<grid, 256, HMM_SMEM_BYTES>>>(xn, wqh, qkv_b, qkv, nullptr,
                                                     TOKENS, 3 * DIM, DIM);
    }

    // 3) windowed attention
    {
        dim3 grid(NWIN, NH);
        attn_kernel<<<grid, 256>>>();
    }

    // 4) proj GEMM (fp16) + fused scatter/residual -> g_xa
    {
        dim3 grid(DIM / 128, MPAD / 128);
        hmm_kernel<1><<<grid, 256, HMM_SMEM_BYTES>>>(ao, wph, proj_b, xa, x,
                                                     TOKENS, DIM, DIM);
    }

    // 5) depthwise conv + BN
    {
        size_t total = (size_t)BL * DIM;
        conv_bn_kernel<<<(unsigned)((total + 255) / 256), 256>>>(conv_w, bn_g, bn_b, bn_m, bn_v);
    }

    // 6) LN2
    ln2_kernel<<<BL, 128>>>(ln2_w, ln2_b);

    // 7) fc1 + gelu (tf32)
    {
        dim3 grid(FFN / 128, BL / 128);
        mm_kernel<1><<<grid, 256, MM_SMEM_BYTES>>>(xn2, w1, fc1_b, hbuf, nullptr,
                                                   BL, FFN, DIM);
    }

    // 8) fc2 + residual -> out (tf32)
    {
        dim3 grid(DIM / 128, BL / 128);
        mm_kernel<2><<<grid, 256, MM_SMEM_BYTES>>>(hbuf, w2, fc2_b, out, xb,
                                                   BL, DIM, FFN);
    }
}

// round 7
// speedup vs baseline: 2.7474x; 1.1641x over previous
#include <cuda_runtime.h>
#include <cuda_fp16.h>
#include <math.h>
#include <stdint.h>

#define BATCH 32
#define HH 32
#define WW_ 32
#define L 1024
#define DIM 384
#define NH 12
#define HD 32
#define WS 7
#define NWIN 800
#define NTOK 49
#define TOKENS (NWIN * NTOK)   // 39200
#define MPAD 39296
#define BL (BATCH * L)         // 32768
#define FFN (4 * DIM)          // 1536
#define EPSV 1e-5f

// ---------------- scratch ----------------
__device__ __half g_xn[(size_t)MPAD * DIM];        // LN1 out, fp16
__device__ __half g_qkv[(size_t)MPAD * 3 * DIM];   // qkv, fp16
__device__ __half g_ao[(size_t)MPAD * DIM];        // attn out, fp16
__device__ float  g_xa[(size_t)BL * DIM];          // x + proj (scattered)
__device__ float  g_xb[(size_t)BL * DIM];          // after conv+BN (fc2 residual)
__device__ __half g_xn2[(size_t)BL * DIM];         // LN2 out, fp16
__device__ __half g_h[(size_t)BL * FFN];           // fc1+gelu out, fp16
__device__ __half g_wqh[(size_t)3 * DIM * DIM];    // fp16 transposed weights
__device__ __half g_wph[(size_t)DIM * DIM];
__device__ __half g_w1h[(size_t)FFN * DIM];
__device__ __half g_w2h[(size_t)DIM * FFN];
__device__ float  g_biasf[(size_t)NH * NTOK * NTOK];

// ================= common helpers =================
__device__ __forceinline__ uint32_t s2u(const void* p) {
    uint32_t a;
    asm("{ .reg .u64 t; cvta.to.shared.u64 t, %1; cvt.u32.u64 %0, t; }" : "=r"(a) : "l"(p));
    return a;
}
__device__ __forceinline__ void cp_async16(uint32_t dst, const void* src) {
    asm volatile("cp.async.cg.shared.global [%0], [%1], 16;" :: "r"(dst), "l"(src) : "memory");
}
__device__ __forceinline__ void cp_commit() {
    asm volatile("cp.async.commit_group;" ::: "memory");
}
template <int N>
__device__ __forceinline__ void cp_wait() {
    asm volatile("cp.async.wait_group %0;" :: "n"(N) : "memory");
}
__device__ __forceinline__ uint32_t sw128(uint32_t byte_off) {
    return byte_off ^ ((byte_off >> 3) & 0x70u);
}
__device__ __forceinline__ void ldsm_x4(uint32_t* r, uint32_t addr) {
    asm volatile("ldmatrix.sync.aligned.m8n8.x4.shared.b16 {%0,%1,%2,%3}, [%4];"
                 : "=r"(r[0]), "=r"(r[1]), "=r"(r[2]), "=r"(r[3]) : "r"(addr));
}
__device__ __forceinline__ void mma_f16(float* c, const uint32_t* a, const uint32_t* b) {
    asm volatile("mma.sync.aligned.m16n8k16.row.col.f32.f16.f16.f32 "
                 "{%0,%1,%2,%3}, {%4,%5,%6,%7}, {%8,%9}, {%0,%1,%2,%3};"
                 : "+f"(c[0]), "+f"(c[1]), "+f"(c[2]), "+f"(c[3])
                 : "r"(a[0]), "r"(a[1]), "r"(a[2]), "r"(a[3]), "r"(b[0]), "r"(b[1]));
}
// load one 128x64 fp16 tile (row-major) into SW128-swizzled smem
__device__ __forceinline__ void load_tile_h(const __half* __restrict__ src, int ld,
                                            int k0, uint32_t dst, int tid) {
    #pragma unroll
    for (int i = 0; i < 4; ++i) {
        int idx = i * 256 + tid;
        int r = idx >> 3, f = idx & 7;
        cp_async16(dst + sw128((uint32_t)(r * 128 + f * 16)),
                   src + (size_t)r * ld + k0 + f * 8);
    }
}

// ================ FP16 HMMA GEMM: C[M,N] = A[M,K] @ Bt[N,K]^T + bias ================
// EPI: 0 fp16 out; 1 scatter+residual fp32; 2 gelu -> fp16 out; 3 +R -> fp32 out
#define HMM_SMEM_BYTES 65536
template <int EPI>
__global__ void __launch_bounds__(256) hmm_kernel(const __half* __restrict__ A,
                                                  const __half* __restrict__ Bt,
                                                  const float* __restrict__ bias,
                                                  void* __restrict__ Cout,
                                                  const float* __restrict__ X,
                                                  int M, int N, int K) {
    extern __shared__ char smem[];
    const int tid = threadIdx.x;
    const int wid = tid >> 5, lane = tid & 31;
    const int bx = blockIdx.x, by = blockIdx.y;
    const uint32_t sb = s2u(smem);
    const uint32_t asb[2] = { sb, sb + 16384 };
    const uint32_t bsb[2] = { sb + 32768, sb + 49152 };

    const __half* Abase = A + (size_t)by * 128 * K;
    const __half* Bbase = Bt + (size_t)bx * 128 * K;
    const int nk = K >> 6;

    const int warp_m = (wid >> 2) * 64;
    const int warp_n = (wid & 3) * 32;

    float acc[4][4][4];
    #pragma unroll
    for (int i = 0; i < 4; ++i)
        #pragma unroll
        for (int j = 0; j < 4; ++j)
            #pragma unroll
            for (int q = 0; q < 4; ++q) acc[i][j][q] = 0.f;

    load_tile_h(Abase, K, 0, asb[0], tid);
    load_tile_h(Bbase, K, 0, bsb[0], tid);
    cp_commit();

    const int a_row = (lane & 7) + ((lane >> 3) & 1) * 8;
    const int a_kc  = (lane >> 4) * 8;
    const int b_nr  = (lane & 7) + ((lane >> 4) * 8);
    const int b_kc  = ((lane >> 3) & 1) * 8;

    for (int c = 0; c < nk; ++c) {
        int cur = c & 1;
        if (c + 1 < nk) {
            load_tile_h(Abase, K, (c + 1) * 64, asb[cur ^ 1], tid);
            load_tile_h(Bbase, K, (c + 1) * 64, bsb[cur ^ 1], tid);
            cp_commit();
            cp_wait<1>();
        } else {
            cp_wait<0>();
        }
        __syncthreads();

        #pragma unroll
        for (int ks = 0; ks < 4; ++ks) {
            uint32_t a[4][4];
            #pragma unroll
            for (int mt = 0; mt < 4; ++mt) {
                int row = warp_m + mt * 16 + a_row;
                int kc = ks * 16 + a_kc;
                ldsm_x4(a[mt], asb[cur] + sw128((uint32_t)(row * 128 + kc * 2)));
            }
            uint32_t b[4][2];
            #pragma unroll
            for (int np = 0; np < 2; ++np) {
                uint32_t r4[4];
                int nrow = warp_n + np * 16 + b_nr;
                int kc = ks * 16 + b_kc;
                ldsm_x4(r4, bsb[cur] + sw128((uint32_t)(nrow * 128 + kc * 2)));
                b[np * 2 + 0][0] = r4[0]; b[np * 2 + 0][1] = r4[1];
                b[np * 2 + 1][0] = r4[2]; b[np * 2 + 1][1] = r4[3];
            }
            #pragma unroll
            for (int mt = 0; mt < 4; ++mt)
                #pragma unroll
                for (int nt = 0; nt < 4; ++nt)
                    mma_f16(acc[mt][nt], a[mt], b[nt]);
        }
        __syncthreads();
    }

    const int erow = lane >> 2;
    const int ecol = (lane & 3) * 2;
    #pragma unroll
    for (int nt = 0; nt < 4; ++nt) {
        int gcol = bx * 128 + warp_n + nt * 8 + ecol;
        float b0 = bias[gcol], b1 = bias[gcol + 1];
        #pragma unroll
        for (int mt = 0; mt < 4; ++mt) {
            #pragma unroll
            for (int h = 0; h < 2; ++h) {
                int grow = by * 128 + warp_m + mt * 16 + erow + h * 8;
                if (grow >= M) continue;
                float v0 = acc[mt][nt][h * 2 + 0] + b0;
                float v1 = acc[mt][nt][h * 2 + 1] + b1;
                if (EPI == 0) {
                    __half2 hp = __floats2half2_rn(v0, v1);
                    *reinterpret_cast<__half2*>((__half*)Cout + (size_t)grow * N + gcol) = hp;
                } else if (EPI == 1) {
                    int win = grow / NTOK, t = grow % NTOK;
                    int bb = win / 25, wrem = win % 25;
                    int r = (wrem / 5) * WS + t / WS;
                    int cc = (wrem % 5) * WS + t % WS;
                    if (r < HH && cc < WW_) {
                        size_t base = ((size_t)bb * L + r * WW_ + cc) * DIM + gcol;
                        float2 xv = *reinterpret_cast<const float2*>(X + base);
                        float2 o = make_float2(v0 + xv.x, v1 + xv.y);
                        *reinterpret_cast<float2*>((float*)Cout + base) = o;
                    }
                } else if (EPI == 2) {
                    v0 = 0.5f * v0 * (1.f + erff(v0 * 0.70710678118654752f));
                    v1 = 0.5f * v1 * (1.f + erff(v1 * 0.70710678118654752f));
                    __half2 hp = __floats2half2_rn(v0, v1);
                    *reinterpret_cast<__half2*>((__half*)Cout + (size_t)grow * N + gcol) = hp;
                } else {
                    float2 r2 = *reinterpret_cast<const float2*>(X + (size_t)grow * N + gcol);
                    float2 o = make_float2(v0 + r2.x, v1 + r2.y);
                    *reinterpret_cast<float2*>((float*)Cout + (size_t)grow * N + gcol) = o;
                }
            }
        }
    }
}

// ---------------- weight prep ----------------
__global__ void wt_h_kernel(const float* __restrict__ W, __half* __restrict__ Wt, int K, int N) {
    int idx = blockIdx.x * 256 + threadIdx.x;
    if (idx >= K * N) return;
    int k = idx / N, n = idx % N;
    Wt[(size_t)n * K + k] = __float2half(W[idx]);
}
__global__ void bias_expand_kernel(const float* __restrict__ attn_bias,
                                   const int* __restrict__ bias_idxs) {
    int idx = blockIdx.x * 256 + threadIdx.x;
    if (idx >= NH * NTOK * NTOK) return;
    int h = idx / (NTOK * NTOK), i = idx % (NTOK * NTOK);
    g_biasf[idx] = attn_bias[h * NTOK + bias_idxs[i]];
}

// ---------------- block reduce ----------------
__device__ __forceinline__ void blockReduce2_128(float& a, float& b) {
    __shared__ float sa[4], sb_[4];
    int lane = threadIdx.x & 31, wid = threadIdx.x >> 5;
    #pragma unroll
    for (int o = 16; o > 0; o >>= 1) {
        a += __shfl_down_sync(0xffffffffu, a, o);
        b += __shfl_down_sync(0xffffffffu, b, o);
    }
    if (lane == 0) { sa[wid] = a; sb_[wid] = b; }
    __syncthreads();
    if (threadIdx.x == 0) {
        a = sa[0] + sa[1] + sa[2] + sa[3];
        b = sb_[0] + sb_[1] + sb_[2] + sb_[3];
        sa[0] = a; sb_[0] = b;
    }
    __syncthreads();
    a = sa[0]; b = sb_[0];
    __syncthreads();
}

// ---------------- LN1 + window partition -> fp16 ----------------
__global__ void ln1_window_kernel(const float* __restrict__ x,
                                  const float* __restrict__ w,
                                  const float* __restrict__ b) {
    int g = blockIdx.x;
    int win = g / NTOK, t = g % NTOK;
    int bb = win / 25, wrem = win % 25;
    int wh = wrem / 5, wwi = wrem % 5;
    int i = t / WS, j = t % WS;
    int row = wh * WS + i, col = wwi * WS + j;
    bool valid = (row < HH) && (col < WW_);
    const float* xp = x + ((size_t)bb * L + row * WW_ + col) * DIM;
    int tid = threadIdx.x;
    float vals[3];
    float s = 0.f, sq = 0.f;
    #pragma unroll
    for (int c = 0; c < 3; ++c) {
        float v = valid ? xp[tid + c * 128] : 0.f;
        vals[c] = v; s += v; sq += v * v;
    }
    blockReduce2_128(s, sq);
    float mu = s * (1.f / DIM);
    float var = sq * (1.f / DIM) - mu * mu;
    float inv = rsqrtf(var + EPSV);
    __half* op = g_xn + (size_t)g * DIM;
    #pragma unroll
    for (int c = 0; c < 3; ++c) {
        int idx = tid + c * 128;
        op[idx] = __float2half((vals[c] - mu) * inv * w[idx] + b[idx]);
    }
}

// ---------------- fused conv3x3 + BN + LN2 ----------------
// block per token; writes g_xb (fp32, fc2 residual) and g_xn2 (fp16, fc1 input)
__global__ void conv_bn_ln2_kernel(const float* __restrict__ cw,
                                   const float* __restrict__ bg,
                                   const float* __restrict__ bb_,
                                   const float* __restrict__ bm,
                                   const float* __restrict__ bv,
                                   const float* __restrict__ lw,
                                   const float* __restrict__ lb) {
    int g = blockIdx.x;            // token index in [0, BL)
    int l = g % L, bb = g / L;
    int row = l / WW_, col = l % WW_;
    int tid = threadIdx.x;

    float y[3];
    float s = 0.f, sq = 0.f;
    #pragma unroll
    for (int cc3 = 0; cc3 < 3; ++cc3) {
        int c = tid + cc3 * 128;
        float acc = 0.f;
        #pragma unroll
        for (int dh = -1; dh <= 1; ++dh) {
            #pragma unroll
            for (int dw = -1; dw <= 1; ++dw) {
                int r = row + dh, cl = col + dw;
                if (r >= 0 && r < HH && cl >= 0 && cl < WW_) {
                    acc += g_xa[((size_t)bb * L + r * WW_ + cl) * DIM + c] *
                           cw[c * 9 + (dh + 1) * 3 + (dw + 1)];
                }
            }
        }
        float inv = rsqrtf(bv[c] + EPSV);
        float v = (acc - bm[c]) * inv * bg[c] + bb_[c];
        y[cc3] = v;
        g_xb[(size_t)g * DIM + c] = v;
        s += v; sq += v * v;
    }
    blockReduce2_128(s, sq);
    float mu = s * (1.f / DIM);
    float var = sq * (1.f / DIM) - mu * mu;
    float inv2 = rsqrtf(var + EPSV);
    __half* op = g_xn2 + (size_t)g * DIM;
    #pragma unroll
    for (int cc3 = 0; cc3 < 3; ++cc3) {
        int c = tid + cc3 * 128;
        op[c] = __float2half((y[cc3] - mu) * inv2 * lw[c] + lb[c]);
    }
}

// ---------------- fused windowed attention (fp16 qkv) ----------------
__global__ void attn_kernel() {
    int w = blockIdx.x;
    int h = blockIdx.y;
    __shared__ float q[NTOK * HD];
    __shared__ float k[NTOK * HD];
    __shared__ float v[NTOK * HD];
    __shared__ float s[NTOK * 50];
    int tid = threadIdx.x;
    int wid = tid >> 5, lane = tid & 31;
    const __half* base = g_qkv + (size_t)w * NTOK * (3 * DIM);
    for (int i = tid; i < NTOK * HD; i += 256) {
        int t = i / HD, d = i % HD;
        const __half* p = base + (size_t)t * (3 * DIM) + h * 96 + d;
        q[i] = __half2float(p[0]);
        k[i] = __half2float(p[32]);
        v[i] = __half2float(p[64]);
    }
    __syncthreads();
    const float scale = 0.1767766952966369f;
    const float* bf = g_biasf + (size_t)h * NTOK * NTOK;
    for (int i = tid; i < NTOK * NTOK; i += 256) {
        int n = i / NTOK, m = i % NTOK;
        float acc = 0.f;
        #pragma unroll
        for (int d = 0; d < HD; ++d) acc += q[n * HD + d] * k[m * HD + d];
        s[n * 50 + m] = acc * scale + bf[i];
    }
    __syncthreads();
    for (int r = wid; r < NTOK; r += 8) {
        float v0 = (lane < NTOK) ? s[r * 50 + lane] : -1e30f;
        float v1 = (lane + 32 < NTOK) ? s[r * 50 + lane + 32] : -1e30f;
        float mx = fmaxf(v0, v1);
        #pragma unroll
        for (int o = 16; o > 0; o >>= 1) mx = fmaxf(mx, __shfl_xor_sync(0xffffffffu, mx, o));
        float e0 = (lane < NTOK) ? expf(v0 - mx) : 0.f;
        float e1 = (lane + 32 < NTOK) ? expf(v1 - mx) : 0.f;
        float sum = e0 + e1;
        #pragma unroll
        for (int o = 16; o > 0; o >>= 1) sum += __shfl_xor_sync(0xffffffffu, sum, o);
        float inv = 1.f / sum;
        if (lane < NTOK) s[r * 50 + lane] = e0 * inv;
        if (lane + 32 < NTOK) s[r * 50 + lane + 32] = e1 * inv;
    }
    __syncthreads();
    for (int i = tid; i < NTOK * HD; i += 256) {
        int n = i / HD, d = i % HD;
        float acc = 0.f;
        #pragma unroll 7
        for (int m = 0; m < NTOK; ++m) acc += s[n * 50 + m] * v[m * HD + d];
        g_ao[((size_t)w * NTOK + n) * DIM + h * HD + d] = __float2half(acc);
    }
}

// ---------------- launch ----------------
extern "C" void kernel_launch(void* const* d_in, const int* in_sizes, int n_in,
                              void* d_out, int out_size) {
    const float* x         = (const float*)d_in[0];
    const float* ln1_w     = (const float*)d_in[1];
    const float* ln1_b     = (const float*)d_in[2];
    const float* qkv_w     = (const float*)d_in[3];
    const float* qkv_b     = (const float*)d_in[4];
    const float* proj_w    = (const float*)d_in[5];
    const float* proj_b    = (const float*)d_in[6];
    const float* attn_bias = (const float*)d_in[7];
    const int*   bias_idxs = (const int*)d_in[8];
    const float* conv_w    = (const float*)d_in[9];
    const float* bn_g      = (const float*)d_in[10];
    const float* bn_b      = (const float*)d_in[11];
    const float* bn_m      = (const float*)d_in[12];
    const float* bn_v      = (const float*)d_in[13];
    const float* ln2_w     = (const float*)d_in[14];
    const float* ln2_b     = (const float*)d_in[15];
    const float* fc1_w     = (const float*)d_in[16];
    const float* fc1_b     = (const float*)d_in[17];
    const float* fc2_w     = (const float*)d_in[18];
    const float* fc2_b     = (const float*)d_in[19];
    float* out = (float*)d_out;

    __half *xn, *qkv, *ao, *xn2, *hbuf, *wqh, *wph, *w1h, *w2h;
    float *xa, *xb;
    cudaGetSymbolAddress((void**)&xn,  g_xn);
    cudaGetSymbolAddress((void**)&qkv, g_qkv);
    cudaGetSymbolAddress((void**)&ao,  g_ao);
    cudaGetSymbolAddress((void**)&xa,  g_xa);
    cudaGetSymbolAddress((void**)&xb,  g_xb);
    cudaGetSymbolAddress((void**)&xn2, g_xn2);
    cudaGetSymbolAddress((void**)&hbuf, g_h);
    cudaGetSymbolAddress((void**)&wqh, g_wqh);
    cudaGetSymbolAddress((void**)&wph, g_wph);
    cudaGetSymbolAddress((void**)&w1h, g_w1h);
    cudaGetSymbolAddress((void**)&w2h, g_w2h);

    cudaFuncSetAttribute(hmm_kernel<0>, cudaFuncAttributeMaxDynamicSharedMemorySize, HMM_SMEM_BYTES);
    cudaFuncSetAttribute(hmm_kernel<1>, cudaFuncAttributeMaxDynamicSharedMemorySize, HMM_SMEM_BYTES);
    cudaFuncSetAttribute(hmm_kernel<2>, cudaFuncAttributeMaxDynamicSharedMemorySize, HMM_SMEM_BYTES);
    cudaFuncSetAttribute(hmm_kernel<3>, cudaFuncAttributeMaxDynamicSharedMemorySize, HMM_SMEM_BYTES);

    // 0) weight prep + bias expansion
    wt_h_kernel<<<(DIM * 3 * DIM + 255) / 256, 256>>>(qkv_w, wqh, DIM, 3 * DIM);
    wt_h_kernel<<<(DIM * DIM + 255) / 256, 256>>>(proj_w, wph, DIM, DIM);
    wt_h_kernel<<<(DIM * FFN + 255) / 256, 256>>>(fc1_w, w1h, DIM, FFN);
    wt_h_kernel<<<(FFN * DIM + 255) / 256, 256>>>(fc2_w, w2h, FFN, DIM);
    bias_expand_kernel<<<(NH * NTOK * NTOK + 255) / 256, 256>>>(attn_bias, bias_idxs);

    // 1) LN1 + window partition (fp16)
    ln1_window_kernel<<<TOKENS, 128>>>(x, ln1_w, ln1_b);

    // 2) qkv GEMM (fp16)
    {
        dim3 grid((3 * DIM) / 128, MPAD / 128);
        hmm_kernel<0><<<grid, 256, HMM_SMEM_BYTES>>>(xn, wqh, qkv_b, qkv, nullptr,
                                                     TOKENS, 3 * DIM, DIM);
    }

    // 3) windowed attention
    {
        dim3 grid(NWIN, NH);
        attn_kernel<<<grid, 256>>>();
    }

    // 4) proj GEMM (fp16) + fused scatter/residual -> g_xa
    {
        dim3 grid(DIM / 128, MPAD / 128);
        hmm_kernel<1><<<grid, 256, HMM_SMEM_BYTES>>>(ao, wph, proj_b, xa, x,
                                                     TOKENS, DIM, DIM);
    }

    // 5) conv + BN + LN2 (fused)
    conv_bn_ln2_kernel<<<BL, 128>>>(conv_w, bn_g, bn_b, bn_m, bn_v, ln2_w, ln2_b);

    // 6) fc1 + gelu (fp16) -> fp16
    {
        dim3 grid(FFN / 128, BL / 128);
        hmm_kernel<2><<<grid, 256, HMM_SMEM_BYTES>>>(xn2, w1h, fc1_b, hbuf, nullptr,
                                                     BL, FFN, DIM);
    }

    // 7) fc2 + residual -> out (fp16 math, fp32 out)
    {
        dim3 grid(DIM / 128, BL / 128);
        hmm_kernel<3><<<grid, 256, HMM_SMEM_BYTES>>>(hbuf, w2h, fc2_b, out, xb,
                                                     BL, DIM, FFN);
    }
}

// round 8
// speedup vs baseline: 2.7552x; 1.0029x over previous
#include <cuda_runtime.h>
#include <cuda_fp16.h>
#include <math.h>
#include <stdint.h>

#define BATCH 32
#define HH 32
#define WW_ 32
#define L 1024
#define DIM 384
#define NH 12
#define HD 32
#define WS 7
#define NWIN 800
#define NTOK 49
#define TOKENS (NWIN * NTOK)   // 39200
#define MPAD 39296
#define BL (BATCH * L)         // 32768
#define FFN (4 * DIM)          // 1536
#define EPSV 1e-5f

// ---------------- scratch ----------------
__device__ __half g_xn[(size_t)MPAD * DIM];
__device__ __half g_qkv[(size_t)MPAD * 3 * DIM];
__device__ __half g_ao[(size_t)MPAD * DIM];
__device__ float  g_xa[(size_t)BL * DIM];
__device__ float  g_xb[(size_t)BL * DIM];
__device__ __half g_xn2[(size_t)BL * DIM];
__device__ __half g_h[(size_t)BL * FFN];
__device__ __half g_wqh[(size_t)3 * DIM * DIM];
__device__ __half g_wph[(size_t)DIM * DIM];
__device__ __half g_w1h[(size_t)FFN * DIM];
__device__ __half g_w2h[(size_t)DIM * FFN];
__device__ float  g_biasf[(size_t)NH * NTOK * NTOK];

// ================= common helpers =================
__device__ __forceinline__ uint32_t s2u(const void* p) {
    uint32_t a;
    asm("{ .reg .u64 t; cvta.to.shared.u64 t, %1; cvt.u32.u64 %0, t; }" : "=r"(a) : "l"(p));
    return a;
}
__device__ __forceinline__ void cp_async16(uint32_t dst, const void* src) {
    asm volatile("cp.async.cg.shared.global [%0], [%1], 16;" :: "r"(dst), "l"(src) : "memory");
}
__device__ __forceinline__ void cp_commit() {
    asm volatile("cp.async.commit_group;" ::: "memory");
}
template <int N>
__device__ __forceinline__ void cp_wait() {
    asm volatile("cp.async.wait_group %0;" :: "n"(N) : "memory");
}
__device__ __forceinline__ uint32_t sw128(uint32_t byte_off) {
    return byte_off ^ ((byte_off >> 3) & 0x70u);
}
__device__ __forceinline__ void ldsm_x4(uint32_t* r, uint32_t addr) {
    asm volatile("ldmatrix.sync.aligned.m8n8.x4.shared.b16 {%0,%1,%2,%3}, [%4];"
                 : "=r"(r[0]), "=r"(r[1]), "=r"(r[2]), "=r"(r[3]) : "r"(addr));
}
__device__ __forceinline__ void mma_f16(float* c, const uint32_t* a, const uint32_t* b) {
    asm volatile("mma.sync.aligned.m16n8k16.row.col.f32.f16.f16.f32 "
                 "{%0,%1,%2,%3}, {%4,%5,%6,%7}, {%8,%9}, {%0,%1,%2,%3};"
                 : "+f"(c[0]), "+f"(c[1]), "+f"(c[2]), "+f"(c[3])
                 : "r"(a[0]), "r"(a[1]), "r"(a[2]), "r"(a[3]), "r"(b[0]), "r"(b[1]));
}
// load one 128x64 fp16 tile (row-major) into SW128-swizzled smem
__device__ __forceinline__ void load_tile_h(const __half* __restrict__ src, int ld,
                                            int k0, uint32_t dst, int tid) {
    #pragma unroll
    for (int i = 0; i < 4; ++i) {
        int idx = i * 256 + tid;
        int r = idx >> 3, f = idx & 7;
        cp_async16(dst + sw128((uint32_t)(r * 128 + f * 16)),
                   src + (size_t)r * ld + k0 + f * 8);
    }
}

// ================ FP16 HMMA GEMM, 3-stage pipeline ================
// EPI: 0 fp16 out; 1 scatter+residual fp32; 2 gelu -> fp16 out; 3 +R -> fp32 out
#define HMM_SMEM_BYTES 98304
template <int EPI>
__global__ void __launch_bounds__(256) hmm_kernel(const __half* __restrict__ A,
                                                  const __half* __restrict__ Bt,
                                                  const float* __restrict__ bias,
                                                  void* __restrict__ Cout,
                                                  const float* __restrict__ X,
                                                  int M, int N, int K) {
    extern __shared__ char smem[];
    const int tid = threadIdx.x;
    const int wid = tid >> 5, lane = tid & 31;
    const int bx = blockIdx.x, by = blockIdx.y;
    const uint32_t sb = s2u(smem);
    uint32_t asb[3], bsb[3];
    #pragma unroll
    for (int s = 0; s < 3; ++s) { asb[s] = sb + s * 16384; bsb[s] = sb + 49152 + s * 16384; }

    const __half* Abase = A + (size_t)by * 128 * K;
    const __half* Bbase = Bt + (size_t)bx * 128 * K;
    const int nk = K >> 6;

    const int warp_m = (wid >> 2) * 64;
    const int warp_n = (wid & 3) * 32;

    float acc[4][4][4];
    #pragma unroll
    for (int i = 0; i < 4; ++i)
        #pragma unroll
        for (int j = 0; j < 4; ++j)
            #pragma unroll
            for (int q = 0; q < 4; ++q) acc[i][j][q] = 0.f;

    // prologue: stages 0 and 1
    load_tile_h(Abase, K, 0, asb[0], tid);
    load_tile_h(Bbase, K, 0, bsb[0], tid);
    cp_commit();
    if (nk > 1) {
        load_tile_h(Abase, K, 64, asb[1], tid);
        load_tile_h(Bbase, K, 64, bsb[1], tid);
    }
    cp_commit();

    const int a_row = (lane & 7) + ((lane >> 3) & 1) * 8;
    const int a_kc  = (lane >> 4) * 8;
    const int b_nr  = (lane & 7) + ((lane >> 4) * 8);
    const int b_kc  = ((lane >> 3) & 1) * 8;

    for (int c = 0; c < nk; ++c) {
        if (c == nk - 1) cp_wait<0>(); else cp_wait<1>();
        __syncthreads();
        const int cur = c % 3;
        const uint32_t abuf = asb[cur];
        const uint32_t bbuf = bsb[cur];

        #pragma unroll
        for (int ks = 0; ks < 4; ++ks) {
            uint32_t a[4][4];
            #pragma unroll
            for (int mt = 0; mt < 4; ++mt) {
                int row = warp_m + mt * 16 + a_row;
                int kc = ks * 16 + a_kc;
                ldsm_x4(a[mt], abuf + sw128((uint32_t)(row * 128 + kc * 2)));
            }
            uint32_t b[4][2];
            #pragma unroll
            for (int np = 0; np < 2; ++np) {
                uint32_t r4[4];
                int nrow = warp_n + np * 16 + b_nr;
                int kc = ks * 16 + b_kc;
                ldsm_x4(r4, bbuf + sw128((uint32_t)(nrow * 128 + kc * 2)));
                b[np * 2 + 0][0] = r4[0]; b[np * 2 + 0][1] = r4[1];
                b[np * 2 + 1][0] = r4[2]; b[np * 2 + 1][1] = r4[3];
            }
            #pragma unroll
            for (int mt = 0; mt < 4; ++mt)
                #pragma unroll
                for (int nt = 0; nt < 4; ++nt)
                    mma_f16(acc[mt][nt], a[mt], b[nt]);
        }
        // prefetch stage c+2 (its buffer was consumed in iter c-1; all warps
        // passed this iter's barrier, so it is free)
        if (c + 2 < nk) {
            int ns = (c + 2) % 3;
            load_tile_h(Abase, K, (c + 2) * 64, asb[ns], tid);
            load_tile_h(Bbase, K, (c + 2) * 64, bsb[ns], tid);
        }
        cp_commit();
    }

    const int erow = lane >> 2;
    const int ecol = (lane & 3) * 2;
    #pragma unroll
    for (int nt = 0; nt < 4; ++nt) {
        int gcol = bx * 128 + warp_n + nt * 8 + ecol;
        float b0 = bias[gcol], b1 = bias[gcol + 1];
        #pragma unroll
        for (int mt = 0; mt < 4; ++mt) {
            #pragma unroll
            for (int h = 0; h < 2; ++h) {
                int grow = by * 128 + warp_m + mt * 16 + erow + h * 8;
                if (grow >= M) continue;
                float v0 = acc[mt][nt][h * 2 + 0] + b0;
                float v1 = acc[mt][nt][h * 2 + 1] + b1;
                if (EPI == 0) {
                    __half2 hp = __floats2half2_rn(v0, v1);
                    *reinterpret_cast<__half2*>((__half*)Cout + (size_t)grow * N + gcol) = hp;
                } else if (EPI == 1) {
                    int win = grow / NTOK, t = grow % NTOK;
                    int bb = win / 25, wrem = win % 25;
                    int r = (wrem / 5) * WS + t / WS;
                    int cc = (wrem % 5) * WS + t % WS;
                    if (r < HH && cc < WW_) {
                        size_t base = ((size_t)bb * L + r * WW_ + cc) * DIM + gcol;
                        float2 xv = *reinterpret_cast<const float2*>(X + base);
                        float2 o = make_float2(v0 + xv.x, v1 + xv.y);
                        *reinterpret_cast<float2*>((float*)Cout + base) = o;
                    }
                } else if (EPI == 2) {
                    v0 = 0.5f * v0 * (1.f + erff(v0 * 0.70710678118654752f));
                    v1 = 0.5f * v1 * (1.f + erff(v1 * 0.70710678118654752f));
                    __half2 hp = __floats2half2_rn(v0, v1);
                    *reinterpret_cast<__half2*>((__half*)Cout + (size_t)grow * N + gcol) = hp;
                } else {
                    float2 r2 = *reinterpret_cast<const float2*>(X + (size_t)grow * N + gcol);
                    float2 o = make_float2(v0 + r2.x, v1 + r2.y);
                    *reinterpret_cast<float2*>((float*)Cout + (size_t)grow * N + gcol) = o;
                }
            }
        }
    }
}

// ---------------- fused prep: 4 weight transposes + bias expansion ----------------
#define WQ_E (DIM * 3 * DIM)      // 442368
#define WP_E (DIM * DIM)          // 147456
#define W1_E (DIM * FFN)          // 589824
#define W2_E (FFN * DIM)          // 589824
#define BI_E (NH * NTOK * NTOK)   // 28812
#define PREP_TOTAL (WQ_E + WP_E + W1_E + W2_E + BI_E)
__global__ void prep_kernel(const float* __restrict__ qkv_w,
                            const float* __restrict__ proj_w,
                            const float* __restrict__ fc1_w,
                            const float* __restrict__ fc2_w,
                            const float* __restrict__ attn_bias,
                            const int* __restrict__ bias_idxs) {
    int idx = blockIdx.x * 256 + threadIdx.x;
    if (idx < WQ_E) {
        int k = idx / (3 * DIM), n = idx % (3 * DIM);
        g_wqh[(size_t)n * DIM + k] = __float2half(qkv_w[idx]);
        return;
    }
    idx -= WQ_E;
    if (idx < WP_E) {
        int k = idx / DIM, n = idx % DIM;
        g_wph[(size_t)n * DIM + k] = __float2half(proj_w[idx]);
        return;
    }
    idx -= WP_E;
    if (idx < W1_E) {
        int k = idx / FFN, n = idx % FFN;
        g_w1h[(size_t)n * DIM + k] = __float2half(fc1_w[idx]);
        return;
    }
    idx -= W1_E;
    if (idx < W2_E) {
        int k = idx / DIM, n = idx % DIM;
        g_w2h[(size_t)n * FFN + k] = __float2half(fc2_w[idx]);
        return;
    }
    idx -= W2_E;
    if (idx < BI_E) {
        int h = idx / (NTOK * NTOK), i = idx % (NTOK * NTOK);
        g_biasf[idx] = attn_bias[h * NTOK + bias_idxs[i]];
    }
}

// ---------------- block reduce ----------------
__device__ __forceinline__ void blockReduce2_128(float& a, float& b) {
    __shared__ float sa[4], sb_[4];
    int lane = threadIdx.x & 31, wid = threadIdx.x >> 5;
    #pragma unroll
    for (int o = 16; o > 0; o >>= 1) {
        a += __shfl_down_sync(0xffffffffu, a, o);
        b += __shfl_down_sync(0xffffffffu, b, o);
    }
    if (lane == 0) { sa[wid] = a; sb_[wid] = b; }
    __syncthreads();
    if (threadIdx.x == 0) {
        a = sa[0] + sa[1] + sa[2] + sa[3];
        b = sb_[0] + sb_[1] + sb_[2] + sb_[3];
        sa[0] = a; sb_[0] = b;
    }
    __syncthreads();
    a = sa[0]; b = sb_[0];
    __syncthreads();
}

// ---------------- LN1 + window partition -> fp16 ----------------
__global__ void ln1_window_kernel(const float* __restrict__ x,
                                  const float* __restrict__ w,
                                  const float* __restrict__ b) {
    int g = blockIdx.x;
    int win = g / NTOK, t = g % NTOK;
    int bb = win / 25, wrem = win % 25;
    int wh = wrem / 5, wwi = wrem % 5;
    int i = t / WS, j = t % WS;
    int row = wh * WS + i, col = wwi * WS + j;
    bool valid = (row < HH) && (col < WW_);
    const float* xp = x + ((size_t)bb * L + row * WW_ + col) * DIM;
    int tid = threadIdx.x;
    float vals[3];
    float s = 0.f, sq = 0.f;
    #pragma unroll
    for (int c = 0; c < 3; ++c) {
        float v = valid ? xp[tid + c * 128] : 0.f;
        vals[c] = v; s += v; sq += v * v;
    }
    blockReduce2_128(s, sq);
    float mu = s * (1.f / DIM);
    float var = sq * (1.f / DIM) - mu * mu;
    float inv = rsqrtf(var + EPSV);
    __half* op = g_xn + (size_t)g * DIM;
    #pragma unroll
    for (int c = 0; c < 3; ++c) {
        int idx = tid + c * 128;
        op[idx] = __float2half((vals[c] - mu) * inv * w[idx] + b[idx]);
    }
}

// ---------------- fused conv3x3 + BN + LN2 ----------------
__global__ void conv_bn_ln2_kernel(const float* __restrict__ cw,
                                   const float* __restrict__ bg,
                                   const float* __restrict__ bb_,
                                   const float* __restrict__ bm,
                                   const float* __restrict__ bv,
                                   const float* __restrict__ lw,
                                   const float* __restrict__ lb) {
    int g = blockIdx.x;
    int l = g % L, bb = g / L;
    int row = l / WW_, col = l % WW_;
    int tid = threadIdx.x;

    float y[3];
    float s = 0.f, sq = 0.f;
    #pragma unroll
    for (int cc3 = 0; cc3 < 3; ++cc3) {
        int c = tid + cc3 * 128;
        float acc = 0.f;
        #pragma unroll
        for (int dh = -1; dh <= 1; ++dh) {
            #pragma unroll
            for (int dw = -1; dw <= 1; ++dw) {
                int r = row + dh, cl = col + dw;
                if (r >= 0 && r < HH && cl >= 0 && cl < WW_) {
                    acc += g_xa[((size_t)bb * L + r * WW_ + cl) * DIM + c] *
                           cw[c * 9 + (dh + 1) * 3 + (dw + 1)];
                }
            }
        }
        float inv = rsqrtf(bv[c] + EPSV);
        float v = (acc - bm[c]) * inv * bg[c] + bb_[c];
        y[cc3] = v;
        g_xb[(size_t)g * DIM + c] = v;
        s += v; sq += v * v;
    }
    blockReduce2_128(s, sq);
    float mu = s * (1.f / DIM);
    float var = sq * (1.f / DIM) - mu * mu;
    float inv2 = rsqrtf(var + EPSV);
    __half* op = g_xn2 + (size_t)g * DIM;
    #pragma unroll
    for (int cc3 = 0; cc3 < 3; ++cc3) {
        int c = tid + cc3 * 128;
        op[c] = __float2half((y[cc3] - mu) * inv2 * lw[c] + lb[c]);
    }
}

// ---------------- fused windowed attention ----------------
__global__ void attn_kernel() {
    int w = blockIdx.x;
    int h = blockIdx.y;
    __shared__ float q[NTOK * HD];
    __shared__ float k[NTOK * HD];
    __shared__ float v[NTOK * HD];
    __shared__ float s[NTOK * 50];
    int tid = threadIdx.x;
    int wid = tid >> 5, lane = tid & 31;
    const __half* base = g_qkv + (size_t)w * NTOK * (3 * DIM);
    for (int i = tid; i < NTOK * HD / 2; i += 256) {
        int t = i / (HD / 2), d2 = i % (HD / 2);
        const __half2* p = reinterpret_cast<const __half2*>(
            base + (size_t)t * (3 * DIM) + h * 96) + d2;
        float2 qf = __half22float2(p[0]);
        float2 kf = __half22float2(p[16]);
        float2 vf = __half22float2(p[32]);
        *reinterpret_cast<float2*>(q + t * HD + d2 * 2) = qf;
        *reinterpret_cast<float2*>(k + t * HD + d2 * 2) = kf;
        *reinterpret_cast<float2*>(v + t * HD + d2 * 2) = vf;
    }
    __syncthreads();
    const float scale = 0.1767766952966369f;
    const float* bf = g_biasf + (size_t)h * NTOK * NTOK;
    for (int i = tid; i < NTOK * NTOK; i += 256) {
        int n = i / NTOK, m = i % NTOK;
        const float4* qn = reinterpret_cast<const float4*>(q + n * HD);
        const float4* km = reinterpret_cast<const float4*>(k + m * HD);
        float acc = 0.f;
        #pragma unroll
        for (int d4 = 0; d4 < HD / 4; ++d4) {
            float4 a4 = qn[d4], b4 = km[d4];
            acc += a4.x * b4.x + a4.y * b4.y + a4.z * b4.z + a4.w * b4.w;
        }
        s[n * 50 + m] = acc * scale + bf[i];
    }
    __syncthreads();
    for (int r = wid; r < NTOK; r += 8) {
        float v0 = (lane < NTOK) ? s[r * 50 + lane] : -1e30f;
        float v1 = (lane + 32 < NTOK) ? s[r * 50 + lane + 32] : -1e30f;
        float mx = fmaxf(v0, v1);
        #pragma unroll
        for (int o = 16; o > 0; o >>= 1) mx = fmaxf(mx, __shfl_xor_sync(0xffffffffu, mx, o));
        float e0 = (lane < NTOK) ? expf(v0 - mx) : 0.f;
        float e1 = (lane + 32 < NTOK) ? expf(v1 - mx) : 0.f;
        float sum = e0 + e1;
        #pragma unroll
        for (int o = 16; o > 0; o >>= 1) sum += __shfl_xor_sync(0xffffffffu, sum, o);
        float inv = 1.f / sum;
        if (lane < NTOK) s[r * 50 + lane] = e0 * inv;
        if (lane + 32 < NTOK) s[r * 50 + lane + 32] = e1 * inv;
    }
    __syncthreads();
    for (int i = tid; i < NTOK * HD; i += 256) {
        int n = i / HD, d = i % HD;
        float acc = 0.f;
        #pragma unroll 7
        for (int m = 0; m < NTOK; ++m) acc += s[n * 50 + m] * v[m * HD + d];
        g_ao[((size_t)w * NTOK + n) * DIM + h * HD + d] = __float2half(acc);
    }
}

// ---------------- launch ----------------
extern "C" void kernel_launch(void* const* d_in, const int* in_sizes, int n_in,
                              void* d_out, int out_size) {
    const float* x         = (const float*)d_in[0];
    const float* ln1_w     = (const float*)d_in[1];
    const float* ln1_b     = (const float*)d_in[2];
    const float* qkv_w     = (const float*)d_in[3];
    const float* qkv_b     = (const float*)d_in[4];
    const float* proj_w    = (const float*)d_in[5];
    const float* proj_b    = (const float*)d_in[6];
    const float* attn_bias = (const float*)d_in[7];
    const int*   bias_idxs = (const int*)d_in[8];
    const float* conv_w    = (const float*)d_in[9];
    const float* bn_g      = (const float*)d_in[10];
    const float* bn_b      = (const float*)d_in[11];
    const float* bn_m      = (const float*)d_in[12];
    const float* bn_v      = (const float*)d_in[13];
    const float* ln2_w     = (const float*)d_in[14];
    const float* ln2_b     = (const float*)d_in[15];
    const float* fc1_w     = (const float*)d_in[16];
    const float* fc1_b     = (const float*)d_in[17];
    const float* fc2_w     = (const float*)d_in[18];
    const float* fc2_b     = (const float*)d_in[19];
    float* out = (float*)d_out;

    __half *xn, *qkv, *ao, *xn2, *hbuf, *wqh, *wph, *w1h, *w2h;
    float *xa, *xb;
    cudaGetSymbolAddress((void**)&xn,  g_xn);
    cudaGetSymbolAddress((void**)&qkv, g_qkv);
    cudaGetSymbolAddress((void**)&ao,  g_ao);
    cudaGetSymbolAddress((void**)&xa,  g_xa);
    cudaGetSymbolAddress((void**)&xb,  g_xb);
    cudaGetSymbolAddress((void**)&xn2, g_xn2);
    cudaGetSymbolAddress((void**)&hbuf, g_h);
    cudaGetSymbolAddress((void**)&wqh, g_wqh);
    cudaGetSymbolAddress((void**)&wph, g_wph);
    cudaGetSymbolAddress((void**)&w1h, g_w1h);
    cudaGetSymbolAddress((void**)&w2h, g_w2h);

    cudaFuncSetAttribute(hmm_kernel<0>, cudaFuncAttributeMaxDynamicSharedMemorySize, HMM_SMEM_BYTES);
    cudaFuncSetAttribute(hmm_kernel<1>, cudaFuncAttributeMaxDynamicSharedMemorySize, HMM_SMEM_BYTES);
    cudaFuncSetAttribute(hmm_kernel<2>, cudaFuncAttributeMaxDynamicSharedMemorySize, HMM_SMEM_BYTES);
    cudaFuncSetAttribute(hmm_kernel<3>, cudaFuncAttributeMaxDynamicSharedMemorySize, HMM_SMEM_BYTES);

    // 0) fused prep (weights + bias)
    prep_kernel<<<(PREP_TOTAL + 255) / 256, 256>>>(qkv_w, proj_w, fc1_w, fc2_w,
                                                   attn_bias, bias_idxs);

    // 1) LN1 + window partition (fp16)
    ln1_window_kernel<<<TOKENS, 128>>>(x, ln1_w, ln1_b);

    // 2) qkv GEMM (fp16)
    {
        dim3 grid((3 * DIM) / 128, MPAD / 128);
        hmm_kernel<0><<<grid, 256, HMM_SMEM_BYTES>>>(xn, wqh, qkv_b, qkv, nullptr,
                                                     TOKENS, 3 * DIM, DIM);
    }

    // 3) windowed attention
    {
        dim3 grid(NWIN, NH);
        attn_kernel<<<grid, 256>>>();
    }

    // 4) proj GEMM (fp16) + fused scatter/residual -> g_xa
    {
        dim3 grid(DIM / 128, MPAD / 128);
        hmm_kernel<1><<<grid, 256, HMM_SMEM_BYTES>>>(ao, wph, proj_b, xa, x,
                                                     TOKENS, DIM, DIM);
    }

    // 5) conv + BN + LN2 (fused)
    conv_bn_ln2_kernel<<<BL, 128>>>(conv_w, bn_g, bn_b, bn_m, bn_v, ln2_w, ln2_b);

    // 6) fc1 + gelu (fp16)
    {
        dim3 grid(FFN / 128, BL / 128);
        hmm_kernel<2><<<grid, 256, HMM_SMEM_BYTES>>>(xn2, w1h, fc1_b, hbuf, nullptr,
                                                     BL, FFN, DIM);
    }

    // 7) fc2 + residual -> out
    {
        dim3 grid(DIM / 128, BL / 128);
        hmm_kernel<3><<<grid, 256, HMM_SMEM_BYTES>>>(hbuf, w2h, fc2_b, out, xb,
                                                     BL, DIM, FFN);
    }
}

// round 10
// speedup vs baseline: 5.1958x; 1.8858x over previous
#include <cuda_runtime.h>
#include <cuda_fp16.h>
#include <math.h>
#include <stdint.h>

#define BATCH 32
#define HH 32
#define WW_ 32
#define L 1024
#define DIM 384
#define NH 12
#define HD 32
#define WS 7
#define NWIN 800
#define NTOK 49
#define TOKENS (NWIN * NTOK)   // 39200
#define MPAD 39296
#define BL (BATCH * L)         // 32768
#define FFN (4 * DIM)          // 1536
#define EPSV 1e-5f

// ---------------- scratch ----------------
__device__ __half g_xn[(size_t)MPAD * DIM];
__device__ __half g_qkv[(size_t)MPAD * 3 * DIM];
__device__ __half g_ao[(size_t)MPAD * DIM];
__device__ float  g_xa[(size_t)BL * DIM];
__device__ float  g_xb[(size_t)BL * DIM];
__device__ __half g_xn2[(size_t)BL * DIM];
__device__ __half g_h[(size_t)BL * FFN];
__device__ __half g_wqh[(size_t)3 * DIM * DIM];
__device__ __half g_wph[(size_t)DIM * DIM];
__device__ __half g_w1h[(size_t)FFN * DIM];
__device__ __half g_w2h[(size_t)DIM * FFN];
__device__ float  g_biasf[(size_t)NH * NTOK * NTOK];

// ================= common helpers =================
__device__ __forceinline__ uint32_t s2u(const void* p) {
    uint32_t a;
    asm("{ .reg .u64 t; cvta.to.shared.u64 t, %1; cvt.u32.u64 %0, t; }" : "=r"(a) : "l"(p));
    return a;
}
__device__ __forceinline__ void cp_async16(uint32_t dst, const void* src) {
    asm volatile("cp.async.cg.shared.global [%0], [%1], 16;" :: "r"(dst), "l"(src) : "memory");
}
__device__ __forceinline__ void cp_commit() {
    asm volatile("cp.async.commit_group;" ::: "memory");
}
template <int N>
__device__ __forceinline__ void cp_wait() {
    asm volatile("cp.async.wait_group %0;" :: "n"(N) : "memory");
}
__device__ __forceinline__ uint32_t sw128(uint32_t byte_off) {
    return byte_off ^ ((byte_off >> 3) & 0x70u);
}
__device__ __forceinline__ void ldsm_x4(uint32_t* r, uint32_t addr) {
    asm volatile("ldmatrix.sync.aligned.m8n8.x4.shared.b16 {%0,%1,%2,%3}, [%4];"
                 : "=r"(r[0]), "=r"(r[1]), "=r"(r[2]), "=r"(r[3]) : "r"(addr));
}
__device__ __forceinline__ void mma_f16(float* c, const uint32_t* a, const uint32_t* b) {
    asm volatile("mma.sync.aligned.m16n8k16.row.col.f32.f16.f16.f32 "
                 "{%0,%1,%2,%3}, {%4,%5,%6,%7}, {%8,%9}, {%0,%1,%2,%3};"
                 : "+f"(c[0]), "+f"(c[1]), "+f"(c[2]), "+f"(c[3])
                 : "r"(a[0]), "r"(a[1]), "r"(a[2]), "r"(a[3]), "r"(b[0]), "r"(b[1]));
}
// load one 128x64 fp16 tile (row-major) into SW128-swizzled smem
__device__ __forceinline__ void load_tile_h(const __half* __restrict__ src, int ld,
                                            int k0, uint32_t dst, int tid) {
    #pragma unroll
    for (int i = 0; i < 4; ++i) {
        int idx = i * 256 + tid;
        int r = idx >> 3, f = idx & 7;
        cp_async16(dst + sw128((uint32_t)(r * 128 + f * 16)),
                   src + (size_t)r * ld + k0 + f * 8);
    }
}

// ================ FP16 HMMA GEMM, 3-stage pipeline ================
// EPI: 0 fp16 out; 1 scatter+residual fp32; 2 gelu -> fp16 out; 3 +R -> fp32 out
#define HMM_SMEM_BYTES 98304
template <int EPI>
__global__ void __launch_bounds__(256) hmm_kernel(const __half* __restrict__ A,
                                                  const __half* __restrict__ Bt,
                                                  const float* __restrict__ bias,
                                                  void* __restrict__ Cout,
                                                  const float* __restrict__ X,
                                                  int M, int N, int K) {
    extern __shared__ char smem[];
    const int tid = threadIdx.x;
    const int wid = tid >> 5, lane = tid & 31;
    const int bx = blockIdx.x, by = blockIdx.y;
    const uint32_t sb = s2u(smem);
    uint32_t asb[3], bsb[3];
    #pragma unroll
    for (int s = 0; s < 3; ++s) { asb[s] = sb + s * 16384; bsb[s] = sb + 49152 + s * 16384; }

    const __half* Abase = A + (size_t)by * 128 * K;
    const __half* Bbase = Bt + (size_t)bx * 128 * K;
    const int nk = K >> 6;

    const int warp_m = (wid >> 2) * 64;
    const int warp_n = (wid & 3) * 32;

    float acc[4][4][4];
    #pragma unroll
    for (int i = 0; i < 4; ++i)
        #pragma unroll
        for (int j = 0; j < 4; ++j)
            #pragma unroll
            for (int q = 0; q < 4; ++q) acc[i][j][q] = 0.f;

    load_tile_h(Abase, K, 0, asb[0], tid);
    load_tile_h(Bbase, K, 0, bsb[0], tid);
    cp_commit();
    if (nk > 1) {
        load_tile_h(Abase, K, 64, asb[1], tid);
        load_tile_h(Bbase, K, 64, bsb[1], tid);
    }
    cp_commit();

    const int a_row = (lane & 7) + ((lane >> 3) & 1) * 8;
    const int a_kc  = (lane >> 4) * 8;
    const int b_nr  = (lane & 7) + ((lane >> 4) * 8);
    const int b_kc  = ((lane >> 3) & 1) * 8;

    for (int c = 0; c < nk; ++c) {
        if (c == nk - 1) cp_wait<0>(); else cp_wait<1>();
        __syncthreads();
        const int cur = c % 3;
        const uint32_t abuf = asb[cur];
        const uint32_t bbuf = bsb[cur];

        #pragma unroll
        for (int ks = 0; ks < 4; ++ks) {
            uint32_t a[4][4];
            #pragma unroll
            for (int mt = 0; mt < 4; ++mt) {
                int row = warp_m + mt * 16 + a_row;
                int kc = ks * 16 + a_kc;
                ldsm_x4(a[mt], abuf + sw128((uint32_t)(row * 128 + kc * 2)));
            }
            uint32_t b[4][2];
            #pragma unroll
            for (int np = 0; np < 2; ++np) {
                uint32_t r4[4];
                int nrow = warp_n + np * 16 + b_nr;
                int kc = ks * 16 + b_kc;
                ldsm_x4(r4, bbuf + sw128((uint32_t)(nrow * 128 + kc * 2)));
                b[np * 2 + 0][0] = r4[0]; b[np * 2 + 0][1] = r4[1];
                b[np * 2 + 1][0] = r4[2]; b[np * 2 + 1][1] = r4[3];
            }
            #pragma unroll
            for (int mt = 0; mt < 4; ++mt)
                #pragma unroll
                for (int nt = 0; nt < 4; ++nt)
                    mma_f16(acc[mt][nt], a[mt], b[nt]);
        }
        if (c + 2 < nk) {
            int ns = (c + 2) % 3;
            load_tile_h(Abase, K, (c + 2) * 64, asb[ns], tid);
            load_tile_h(Bbase, K, (c + 2) * 64, bsb[ns], tid);
        }
        cp_commit();
    }

    const int erow = lane >> 2;
    const int ecol = (lane & 3) * 2;
    #pragma unroll
    for (int nt = 0; nt < 4; ++nt) {
        int gcol = bx * 128 + warp_n + nt * 8 + ecol;
        float b0 = bias[gcol], b1 = bias[gcol + 1];
        #pragma unroll
        for (int mt = 0; mt < 4; ++mt) {
            #pragma unroll
            for (int h = 0; h < 2; ++h) {
                int grow = by * 128 + warp_m + mt * 16 + erow + h * 8;
                if (grow >= M) continue;
                float v0 = acc[mt][nt][h * 2 + 0] + b0;
                float v1 = acc[mt][nt][h * 2 + 1] + b1;
                if (EPI == 0) {
                    __half2 hp = __floats2half2_rn(v0, v1);
                    *reinterpret_cast<__half2*>((__half*)Cout + (size_t)grow * N + gcol) = hp;
                } else if (EPI == 1) {
                    int win = grow / NTOK, t = grow % NTOK;
                    int bb = win / 25, wrem = win % 25;
                    int r = (wrem / 5) * WS + t / WS;
                    int cc = (wrem % 5) * WS + t % WS;
                    if (r < HH && cc < WW_) {
                        size_t base = ((size_t)bb * L + r * WW_ + cc) * DIM + gcol;
                        float2 xv = *reinterpret_cast<const float2*>(X + base);
                        float2 o = make_float2(v0 + xv.x, v1 + xv.y);
                        *reinterpret_cast<float2*>((float*)Cout + base) = o;
                    }
                } else if (EPI == 2) {
                    v0 = 0.5f * v0 * (1.f + erff(v0 * 0.70710678118654752f));
                    v1 = 0.5f * v1 * (1.f + erff(v1 * 0.70710678118654752f));
                    __half2 hp = __floats2half2_rn(v0, v1);
                    *reinterpret_cast<__half2*>((__half*)Cout + (size_t)grow * N + gcol) = hp;
                } else {
                    float2 r2 = *reinterpret_cast<const float2*>(X + (size_t)grow * N + gcol);
                    float2 o = make_float2(v0 + r2.x, v1 + r2.y);
                    *reinterpret_cast<float2*>((float*)Cout + (size_t)grow * N + gcol) = o;
                }
            }
        }
    }
}

// ---------------- fused prep ----------------
#define WQ_E (DIM * 3 * DIM)
#define WP_E (DIM * DIM)
#define W1_E (DIM * FFN)
#define W2_E (FFN * DIM)
#define BI_E (NH * NTOK * NTOK)
#define PREP_TOTAL (WQ_E + WP_E + W1_E + W2_E + BI_E)
__global__ void prep_kernel(const float* __restrict__ qkv_w,
                            const float* __restrict__ proj_w,
                            const float* __restrict__ fc1_w,
                            const float* __restrict__ fc2_w,
                            const float* __restrict__ attn_bias,
                            const int* __restrict__ bias_idxs) {
    int idx = blockIdx.x * 256 + threadIdx.x;
    if (idx < WQ_E) {
        int k = idx / (3 * DIM), n = idx % (3 * DIM);
        g_wqh[(size_t)n * DIM + k] = __float2half(qkv_w[idx]);
        return;
    }
    idx -= WQ_E;
    if (idx < WP_E) {
        int k = idx / DIM, n = idx % DIM;
        g_wph[(size_t)n * DIM + k] = __float2half(proj_w[idx]);
        return;
    }
    idx -= WP_E;
    if (idx < W1_E) {
        int k = idx / FFN, n = idx % FFN;
        g_w1h[(size_t)n * DIM + k] = __float2half(fc1_w[idx]);
        return;
    }
    idx -= W1_E;
    if (idx < W2_E) {
        int k = idx / DIM, n = idx % DIM;
        g_w2h[(size_t)n * FFN + k] = __float2half(fc2_w[idx]);
        return;
    }
    idx -= W2_E;
    if (idx < BI_E) {
        int h = idx / (NTOK * NTOK), i = idx % (NTOK * NTOK);
        g_biasf[idx] = attn_bias[h * NTOK + bias_idxs[i]];
    }
}

// ---------------- block reduce ----------------
__device__ __forceinline__ void blockReduce2_128(float& a, float& b) {
    __shared__ float sa[4], sb_[4];
    int lane = threadIdx.x & 31, wid = threadIdx.x >> 5;
    #pragma unroll
    for (int o = 16; o > 0; o >>= 1) {
        a += __shfl_down_sync(0xffffffffu, a, o);
        b += __shfl_down_sync(0xffffffffu, b, o);
    }
    if (lane == 0) { sa[wid] = a; sb_[wid] = b; }
    __syncthreads();
    if (threadIdx.x == 0) {
        a = sa[0] + sa[1] + sa[2] + sa[3];
        b = sb_[0] + sb_[1] + sb_[2] + sb_[3];
        sa[0] = a; sb_[0] = b;
    }
    __syncthreads();
    a = sa[0]; b = sb_[0];
    __syncthreads();
}

// ---------------- LN1 + window partition -> fp16 ----------------
__global__ void ln1_window_kernel(const float* __restrict__ x,
                                  const float* __restrict__ w,
                                  const float* __restrict__ b) {
    int g = blockIdx.x;
    int win = g / NTOK, t = g % NTOK;
    int bb = win / 25, wrem = win % 25;
    int wh = wrem / 5, wwi = wrem % 5;
    int i = t / WS, j = t % WS;
    int row = wh * WS + i, col = wwi * WS + j;
    bool valid = (row < HH) && (col < WW_);
    const float* xp = x + ((size_t)bb * L + row * WW_ + col) * DIM;
    int tid = threadIdx.x;
    float vals[3];
    float s = 0.f, sq = 0.f;
    #pragma unroll
    for (int c = 0; c < 3; ++c) {
        float v = valid ? xp[tid + c * 128] : 0.f;
        vals[c] = v; s += v; sq += v * v;
    }
    blockReduce2_128(s, sq);
    float mu = s * (1.f / DIM);
    float var = sq * (1.f / DIM) - mu * mu;
    float inv = rsqrtf(var + EPSV);
    __half* op = g_xn + (size_t)g * DIM;
    #pragma unroll
    for (int c = 0; c < 3; ++c) {
        int idx = tid + c * 128;
        op[idx] = __float2half((vals[c] - mu) * inv * w[idx] + b[idx]);
    }
}

// ---------------- fused conv3x3 + BN + LN2 ----------------
__global__ void conv_bn_ln2_kernel(const float* __restrict__ cw,
                                   const float* __restrict__ bg,
                                   const float* __restrict__ bb_,
                                   const float* __restrict__ bm,
                                   const float* __restrict__ bv,
                                   const float* __restrict__ lw,
                                   const float* __restrict__ lb) {
    int g = blockIdx.x;
    int l = g % L, bb = g / L;
    int row = l / WW_, col = l % WW_;
    int tid = threadIdx.x;

    float y[3];
    float s = 0.f, sq = 0.f;
    #pragma unroll
    for (int cc3 = 0; cc3 < 3; ++cc3) {
        int c = tid + cc3 * 128;
        float acc = 0.f;
        #pragma unroll
        for (int dh = -1; dh <= 1; ++dh) {
            #pragma unroll
            for (int dw = -1; dw <= 1; ++dw) {
                int r = row + dh, cl = col + dw;
                if (r >= 0 && r < HH && cl >= 0 && cl < WW_) {
                    acc += g_xa[((size_t)bb * L + r * WW_ + cl) * DIM + c] *
                           cw[c * 9 + (dh + 1) * 3 + (dw + 1)];
                }
            }
        }
        float inv = rsqrtf(bv[c] + EPSV);
        float v = (acc - bm[c]) * inv * bg[c] + bb_[c];
        y[cc3] = v;
        g_xb[(size_t)g * DIM + c] = v;
        s += v; sq += v * v;
    }
    blockReduce2_128(s, sq);
    float mu = s * (1.f / DIM);
    float var = sq * (1.f / DIM) - mu * mu;
    float inv2 = rsqrtf(var + EPSV);
    __half* op = g_xn2 + (size_t)g * DIM;
    #pragma unroll
    for (int cc3 = 0; cc3 < 3; ++cc3) {
        int c = tid + cc3 * 128;
        op[c] = __float2half((y[cc3] - mu) * inv2 * lw[c] + lb[c]);
    }
}

// ---------------- tensor-core windowed attention ----------------
// block = (window, head), 128 threads = 4 warps.
// S[64,64] = Q[64,32] @ K^T ; softmax -> P fp16 ; O[64,32] = P @ V
#define VT_STRIDE 72
__global__ void __launch_bounds__(128) attn_kernel() {
    __shared__ __half q[64 * 32];
    __shared__ __half k[64 * 32];
    __shared__ __half vt[32 * VT_STRIDE];
    __shared__ float  sS[NTOK * 64];        // stride 64 (full padded width)
    __shared__ __half p[64 * 64];

    const int w = blockIdx.x;
    const int h = blockIdx.y;
    const int tid = threadIdx.x;
    const int wid = tid >> 5, lane = tid & 31;
    const uint32_t qb = s2u(q), kb = s2u(k), vb = s2u(vt), pb = s2u(p);

    // zero vt (NaN-safety for padded cols; P's zero cols multiply these)
    #pragma unroll
    for (int i = tid; i < 32 * VT_STRIDE / 8; i += 128)
        *reinterpret_cast<uint4*>(vt + i * 8) = make_uint4(0, 0, 0, 0);

    // load q, k as [64][32] fp16 (pad rows garbage-ok), v transposed -> vt[32][72]
    const __half* base = g_qkv + (size_t)w * NTOK * (3 * DIM);
    for (int i = tid; i < NTOK * 16; i += 128) {
        int t = i / 16, d2 = i % 16;
        const __half2* pp = reinterpret_cast<const __half2*>(
            base + (size_t)t * (3 * DIM) + h * 96) + d2;
        __half2 q2 = pp[0], k2 = pp[16], v2 = pp[32];
        *reinterpret_cast<__half2*>(q + t * 32 + d2 * 2) = q2;
        *reinterpret_cast<__half2*>(k + t * 32 + d2 * 2) = k2;
        vt[(d2 * 2 + 0) * VT_STRIDE + t] = __low2half(v2);
        vt[(d2 * 2 + 1) * VT_STRIDE + t] = __high2half(v2);
    }
    __syncthreads();

    const int a_row = (lane & 7) + ((lane >> 3) & 1) * 8;
    const int a_kc  = (lane >> 4) * 8;
    const int b_nr  = (lane & 7) + ((lane >> 4) * 8);
    const int b_kc  = ((lane >> 3) & 1) * 8;
    const int erow = lane >> 2;
    const int ecol = (lane & 3) * 2;
    const int wm = wid * 16;     // warp's 16-row slab

    // ---- S = Q @ K^T  (K=32: 2 k-steps; N=64: 8 n-tiles) ----
    {
        float acc[8][4];
        #pragma unroll
        for (int nt = 0; nt < 8; ++nt)
            #pragma unroll
            for (int qq = 0; qq < 4; ++qq) acc[nt][qq] = 0.f;

        #pragma unroll
        for (int ks = 0; ks < 2; ++ks) {
            uint32_t a[4];
            ldsm_x4(a, qb + (uint32_t)((wm + a_row) * 64 + (ks * 16 + a_kc) * 2));
            uint32_t b[8][2];
            #pragma unroll
            for (int np = 0; np < 4; ++np) {
                uint32_t r4[4];
                ldsm_x4(r4, kb + (uint32_t)((np * 16 + b_nr) * 64 + (ks * 16 + b_kc) * 2));
                b[np * 2 + 0][0] = r4[0]; b[np * 2 + 0][1] = r4[1];
                b[np * 2 + 1][0] = r4[2]; b[np * 2 + 1][1] = r4[3];
            }
            #pragma unroll
            for (int nt = 0; nt < 8; ++nt)
                mma_f16(acc[nt], a, b[nt]);
        }

        // fragment -> sS with scale + bias; cols >= 49 -> -1e30
        const float scale = 0.1767766952966369f;
        const float* bf = g_biasf + (size_t)h * NTOK * NTOK;
        #pragma unroll
        for (int nt = 0; nt < 8; ++nt) {
            #pragma unroll
            for (int hh = 0; hh < 2; ++hh) {
                int row = wm + erow + hh * 8;
                if (row >= NTOK) continue;
                int col = nt * 8 + ecol;
                float v0 = acc[nt][hh * 2 + 0];
                float v1 = acc[nt][hh * 2 + 1];
                sS[row * 64 + col] = (col < NTOK)
                    ? v0 * scale + bf[row * NTOK + col] : -1e30f;
                sS[row * 64 + col + 1] = (col + 1 < NTOK)
                    ? v1 * scale + bf[row * NTOK + col + 1] : -1e30f;
            }
        }
    }
    __syncthreads();

    // ---- softmax rows (warp-parallel), write fp16 P with cols>=49 zeroed ----
    for (int r = wid; r < NTOK; r += 4) {
        float v0 = sS[r * 64 + lane];
        float v1 = sS[r * 64 + lane + 32];
        float mx = fmaxf(v0, v1);
        #pragma unroll
        for (int o = 16; o > 0; o >>= 1) mx = fmaxf(mx, __shfl_xor_sync(0xffffffffu, mx, o));
        float e0 = expf(v0 - mx);                                    // cols<49 real; else exp(-inf)=0
        float e1 = (lane + 32 < NTOK) ? expf(v1 - mx) : 0.f;
        float sum = e0 + e1;
        #pragma unroll
        for (int o = 16; o > 0; o >>= 1) sum += __shfl_xor_sync(0xffffffffu, sum, o);
        float inv = 1.f / sum;
        p[r * 64 + lane] = __float2half(e0 * inv);
        p[r * 64 + lane + 32] = __float2half(e1 * inv);
    }
    __syncthreads();

    // ---- O = P @ V  (K=64: 4 k-steps; N=32: 4 n-tiles) ----
    {
        float acc[4][4];
        #pragma unroll
        for (int nt = 0; nt < 4; ++nt)
            #pragma unroll
            for (int qq = 0; qq < 4; ++qq) acc[nt][qq] = 0.f;

        #pragma unroll
        for (int ks = 0; ks < 4; ++ks) {
            uint32_t a[4];
            ldsm_x4(a, pb + (uint32_t)((wm + a_row) * 128 + (ks * 16 + a_kc) * 2));
            uint32_t b[4][2];
            #pragma unroll
            for (int np = 0; np < 2; ++np) {
                uint32_t r4[4];
                ldsm_x4(r4, vb + (uint32_t)((np * 16 + b_nr) * (VT_STRIDE * 2) + (ks * 16 + b_kc) * 2));
                b[np * 2 + 0][0] = r4[0]; b[np * 2 + 0][1] = r4[1];
                b[np * 2 + 1][0] = r4[2]; b[np * 2 + 1][1] = r4[3];
            }
            #pragma unroll
            for (int nt = 0; nt < 4; ++nt)
                mma_f16(acc[nt], a, b[nt]);
        }

        #pragma unroll
        for (int nt = 0; nt < 4; ++nt) {
            #pragma unroll
            for (int hh = 0; hh < 2; ++hh) {
                int row = wm + erow + hh * 8;
                if (row >= NTOK) continue;
                int col = nt * 8 + ecol;
                __half2 hp = __floats2half2_rn(acc[nt][hh * 2 + 0], acc[nt][hh * 2 + 1]);
                *reinterpret_cast<__half2*>(
                    g_ao + ((size_t)w * NTOK + row) * DIM + h * HD + col) = hp;
            }
        }
    }
}

// ---------------- launch ----------------
extern "C" void kernel_launch(void* const* d_in, const int* in_sizes, int n_in,
                              void* d_out, int out_size) {
    const float* x         = (const float*)d_in[0];
    const float* ln1_w     = (const float*)d_in[1];
    const float* ln1_b     = (const float*)d_in[2];
    const float* qkv_w     = (const float*)d_in[3];
    const float* qkv_b     = (const float*)d_in[4];
    const float* proj_w    = (const float*)d_in[5];
    const float* proj_b    = (const float*)d_in[6];
    const float* attn_bias = (const float*)d_in[7];
    const int*   bias_idxs = (const int*)d_in[8];
    const float* conv_w    = (const float*)d_in[9];
    const float* bn_g      = (const float*)d_in[10];
    const float* bn_b      = (const float*)d_in[11];
    const float* bn_m      = (const float*)d_in[12];
    const float* bn_v      = (const float*)d_in[13];
    const float* ln2_w     = (const float*)d_in[14];
    const float* ln2_b     = (const float*)d_in[15];
    const float* fc1_w     = (const float*)d_in[16];
    const float* fc1_b     = (const float*)d_in[17];
    const float* fc2_w     = (const float*)d_in[18];
    const float* fc2_b     = (const float*)d_in[19];
    float* out = (float*)d_out;

    __half *xn, *qkv, *ao, *xn2, *hbuf, *wqh, *wph, *w1h, *w2h;
    float *xa, *xb;
    cudaGetSymbolAddress((void**)&xn,  g_xn);
    cudaGetSymbolAddress((void**)&qkv, g_qkv);
    cudaGetSymbolAddress((void**)&ao,  g_ao);
    cudaGetSymbolAddress((void**)&xa,  g_xa);
    cudaGetSymbolAddress((void**)&xb,  g_xb);
    cudaGetSymbolAddress((void**)&xn2, g_xn2);
    cudaGetSymbolAddress((void**)&hbuf, g_h);
    cudaGetSymbolAddress((void**)&wqh, g_wqh);
    cudaGetSymbolAddress((void**)&wph, g_wph);
    cudaGetSymbolAddress((void**)&w1h, g_w1h);
    cudaGetSymbolAddress((void**)&w2h, g_w2h);

    cudaFuncSetAttribute(hmm_kernel<0>, cudaFuncAttributeMaxDynamicSharedMemorySize, HMM_SMEM_BYTES);
    cudaFuncSetAttribute(hmm_kernel<1>, cudaFuncAttributeMaxDynamicSharedMemorySize, HMM_SMEM_BYTES);
    cudaFuncSetAttribute(hmm_kernel<2>, cudaFuncAttributeMaxDynamicSharedMemorySize, HMM_SMEM_BYTES);
    cudaFuncSetAttribute(hmm_kernel<3>, cudaFuncAttributeMaxDynamicSharedMemorySize, HMM_SMEM_BYTES);

    // 0) fused prep
    prep_kernel<<<(PREP_TOTAL + 255) / 256, 256>>>(qkv_w, proj_w, fc1_w, fc2_w,
                                                   attn_bias, bias_idxs);

    // 1) LN1 + window partition (fp16)
    ln1_window_kernel<<<TOKENS, 128>>>(x, ln1_w, ln1_b);

    // 2) qkv GEMM (fp16)
    {
        dim3 grid((3 * DIM) / 128, MPAD / 128);
        hmm_kernel<0><<<grid, 256, HMM_SMEM_BYTES>>>(xn, wqh, qkv_b, qkv, nullptr,
                                                     TOKENS, 3 * DIM, DIM);
    }

    // 3) windowed attention (tensor cores)
    {
        dim3 grid(NWIN, NH);
        attn_kernel<<<grid, 128>>>();
    }

    // 4) proj GEMM (fp16) + fused scatter/residual -> g_xa
    {
        dim3 grid(DIM / 128, MPAD / 128);
        hmm_kernel<1><<<grid, 256, HMM_SMEM_BYTES>>>(ao, wph, proj_b, xa, x,
                                                     TOKENS, DIM, DIM);
    }

    // 5) conv + BN + LN2 (fused)
    conv_bn_ln2_kernel<<<BL, 128>>>(conv_w, bn_g, bn_b, bn_m, bn_v, ln2_w, ln2_b);

    // 6) fc1 + gelu (fp16)
    {
        dim3 grid(FFN / 128, BL / 128);
        hmm_kernel<2><<<grid, 256, HMM_SMEM_BYTES>>>(xn2, w1h, fc1_b, hbuf, nullptr,
                                                     BL, FFN, DIM);
    }

    // 7) fc2 + residual -> out
    {
        dim3 grid(DIM / 128, BL / 128);
        hmm_kernel<3><<<grid, 256, HMM_SMEM_BYTES>>>(hbuf, w2h, fc2_b, out, xb,
                                                     BL, DIM, FFN);
    }
}

// round 12
// speedup vs baseline: 5.8140x; 1.1190x over previous
#include <cuda_runtime.h>
#include <cuda_fp16.h>
#include <math.h>
#include <stdint.h>

#define BATCH 32
#define HH 32
#define WW_ 32
#define L 1024
#define DIM 384
#define NH 12
#define HD 32
#define WS 7
#define NWIN 800
#define NTOK 49
#define TOKENS (NWIN * NTOK)   // 39200
#define MPAD 39296
#define BL (BATCH * L)         // 32768
#define FFN (4 * DIM)          // 1536
#define EPSV 1e-5f

// ---------------- scratch ----------------
__device__ __half g_xn[(size_t)MPAD * DIM];
__device__ __half g_qkv[(size_t)MPAD * 3 * DIM];
__device__ __half g_ao[(size_t)MPAD * DIM];
__device__ float  g_xa[(size_t)BL * DIM];
__device__ float  g_xb[(size_t)BL * DIM];
__device__ __half g_xn2[(size_t)BL * DIM];
__device__ __half g_h[(size_t)BL * FFN];
__device__ __half g_wqh[(size_t)3 * DIM * DIM];
__device__ __half g_wph[(size_t)DIM * DIM];
__device__ __half g_w1h[(size_t)FFN * DIM];
__device__ __half g_w2h[(size_t)DIM * FFN];
__device__ float  g_biasf[(size_t)NH * NTOK * NTOK];

// ================= common helpers =================
__device__ __forceinline__ uint32_t s2u(const void* p) {
    uint32_t a;
    asm("{ .reg .u64 t; cvta.to.shared.u64 t, %1; cvt.u32.u64 %0, t; }" : "=r"(a) : "l"(p));
    return a;
}
__device__ __forceinline__ void cp_async16(uint32_t dst, const void* src) {
    asm volatile("cp.async.cg.shared.global [%0], [%1], 16;" :: "r"(dst), "l"(src) : "memory");
}
__device__ __forceinline__ void cp_commit() {
    asm volatile("cp.async.commit_group;" ::: "memory");
}
template <int N>
__device__ __forceinline__ void cp_wait() {
    asm volatile("cp.async.wait_group %0;" :: "n"(N) : "memory");
}
__device__ __forceinline__ uint32_t sw128(uint32_t byte_off) {
    return byte_off ^ ((byte_off >> 3) & 0x70u);
}
__device__ __forceinline__ void ldsm_x4(uint32_t* r, uint32_t addr) {
    asm volatile("ldmatrix.sync.aligned.m8n8.x4.shared.b16 {%0,%1,%2,%3}, [%4];"
                 : "=r"(r[0]), "=r"(r[1]), "=r"(r[2]), "=r"(r[3]) : "r"(addr));
}
__device__ __forceinline__ void mma_f16(float* c, const uint32_t* a, const uint32_t* b) {
    asm volatile("mma.sync.aligned.m16n8k16.row.col.f32.f16.f16.f32 "
                 "{%0,%1,%2,%3}, {%4,%5,%6,%7}, {%8,%9}, {%0,%1,%2,%3};"
                 : "+f"(c[0]), "+f"(c[1]), "+f"(c[2]), "+f"(c[3])
                 : "r"(a[0]), "r"(a[1]), "r"(a[2]), "r"(a[3]), "r"(b[0]), "r"(b[1]));
}
// load one 128x64 fp16 tile (row-major) into SW128-swizzled smem
__device__ __forceinline__ void load_tile_h(const __half* __restrict__ src, int ld,
                                            int k0, uint32_t dst, int tid) {
    #pragma unroll
    for (int i = 0; i < 4; ++i) {
        int idx = i * 256 + tid;
        int r = idx >> 3, f = idx & 7;
        cp_async16(dst + sw128((uint32_t)(r * 128 + f * 16)),
                   src + (size_t)r * ld + k0 + f * 8);
    }
}

// ================ FP16 HMMA GEMM, 3-stage pipeline ================
// EPI: 0 fp16 out; 1 scatter+residual fp32; 2 gelu -> fp16 out; 3 +R -> fp32 out
#define HMM_SMEM_BYTES 98304
template <int EPI>
__global__ void __launch_bounds__(256) hmm_kernel(const __half* __restrict__ A,
                                                  const __half* __restrict__ Bt,
                                                  const float* __restrict__ bias,
                                                  void* __restrict__ Cout,
                                                  const float* __restrict__ X,
                                                  int M, int N, int K) {
    extern __shared__ char smem[];
    const int tid = threadIdx.x;
    const int wid = tid >> 5, lane = tid & 31;
    const int bx = blockIdx.x, by = blockIdx.y;
    const uint32_t sb = s2u(smem);
    uint32_t asb[3], bsb[3];
    #pragma unroll
    for (int s = 0; s < 3; ++s) { asb[s] = sb + s * 16384; bsb[s] = sb + 49152 + s * 16384; }

    const __half* Abase = A + (size_t)by * 128 * K;
    const __half* Bbase = Bt + (size_t)bx * 128 * K;
    const int nk = K >> 6;

    const int warp_m = (wid >> 2) * 64;
    const int warp_n = (wid & 3) * 32;

    float acc[4][4][4];
    #pragma unroll
    for (int i = 0; i < 4; ++i)
        #pragma unroll
        for (int j = 0; j < 4; ++j)
            #pragma unroll
            for (int q = 0; q < 4; ++q) acc[i][j][q] = 0.f;

    load_tile_h(Abase, K, 0, asb[0], tid);
    load_tile_h(Bbase, K, 0, bsb[0], tid);
    cp_commit();
    if (nk > 1) {
        load_tile_h(Abase, K, 64, asb[1], tid);
        load_tile_h(Bbase, K, 64, bsb[1], tid);
    }
    cp_commit();

    const int a_row = (lane & 7) + ((lane >> 3) & 1) * 8;
    const int a_kc  = (lane >> 4) * 8;
    const int b_nr  = (lane & 7) + ((lane >> 4) * 8);
    const int b_kc  = ((lane >> 3) & 1) * 8;

    for (int c = 0; c < nk; ++c) {
        if (c == nk - 1) cp_wait<0>(); else cp_wait<1>();
        __syncthreads();
        const int cur = c % 3;
        const uint32_t abuf = asb[cur];
        const uint32_t bbuf = bsb[cur];

        #pragma unroll
        for (int ks = 0; ks < 4; ++ks) {
            uint32_t a[4][4];
            #pragma unroll
            for (int mt = 0; mt < 4; ++mt) {
                int row = warp_m + mt * 16 + a_row;
                int kc = ks * 16 + a_kc;
                ldsm_x4(a[mt], abuf + sw128((uint32_t)(row * 128 + kc * 2)));
            }
            uint32_t b[4][2];
            #pragma unroll
            for (int np = 0; np < 2; ++np) {
                uint32_t r4[4];
                int nrow = warp_n + np * 16 + b_nr;
                int kc = ks * 16 + b_kc;
                ldsm_x4(r4, bbuf + sw128((uint32_t)(nrow * 128 + kc * 2)));
                b[np * 2 + 0][0] = r4[0]; b[np * 2 + 0][1] = r4[1];
                b[np * 2 + 1][0] = r4[2]; b[np * 2 + 1][1] = r4[3];
            }
            #pragma unroll
            for (int mt = 0; mt < 4; ++mt)
                #pragma unroll
                for (int nt = 0; nt < 4; ++nt)
                    mma_f16(acc[mt][nt], a[mt], b[nt]);
        }
        if (c + 2 < nk) {
            int ns = (c + 2) % 3;
            load_tile_h(Abase, K, (c + 2) * 64, asb[ns], tid);
            load_tile_h(Bbase, K, (c + 2) * 64, bsb[ns], tid);
        }
        cp_commit();
    }

    const int erow = lane >> 2;
    const int ecol = (lane & 3) * 2;
    #pragma unroll
    for (int nt = 0; nt < 4; ++nt) {
        int gcol = bx * 128 + warp_n + nt * 8 + ecol;
        float b0 = bias[gcol], b1 = bias[gcol + 1];
        #pragma unroll
        for (int mt = 0; mt < 4; ++mt) {
            #pragma unroll
            for (int h = 0; h < 2; ++h) {
                int grow = by * 128 + warp_m + mt * 16 + erow + h * 8;
                if (grow >= M) continue;
                float v0 = acc[mt][nt][h * 2 + 0] + b0;
                float v1 = acc[mt][nt][h * 2 + 1] + b1;
                if (EPI == 0) {
                    __half2 hp = __floats2half2_rn(v0, v1);
                    *reinterpret_cast<__half2*>((__half*)Cout + (size_t)grow * N + gcol) = hp;
                } else if (EPI == 1) {
                    int win = grow / NTOK, t = grow % NTOK;
                    int bb = win / 25, wrem = win % 25;
                    int r = (wrem / 5) * WS + t / WS;
                    int cc = (wrem % 5) * WS + t % WS;
                    if (r < HH && cc < WW_) {
                        size_t base = ((size_t)bb * L + r * WW_ + cc) * DIM + gcol;
                        float2 xv = *reinterpret_cast<const float2*>(X + base);
                        float2 o = make_float2(v0 + xv.x, v1 + xv.y);
                        *reinterpret_cast<float2*>((float*)Cout + base) = o;
                    }
                } else if (EPI == 2) {
                    v0 = 0.5f * v0 * (1.f + erff(v0 * 0.70710678118654752f));
                    v1 = 0.5f * v1 * (1.f + erff(v1 * 0.70710678118654752f));
                    __half2 hp = __floats2half2_rn(v0, v1);
                    *reinterpret_cast<__half2*>((__half*)Cout + (size_t)grow * N + gcol) = hp;
                } else {
                    float2 r2 = *reinterpret_cast<const float2*>(X + (size_t)grow * N + gcol);
                    float2 o = make_float2(v0 + r2.x, v1 + r2.y);
                    *reinterpret_cast<float2*>((float*)Cout + (size_t)grow * N + gcol) = o;
                }
            }
        }
    }
}

// ---------------- fused prep ----------------
#define WQ_E (DIM * 3 * DIM)
#define WP_E (DIM * DIM)
#define W1_E (DIM * FFN)
#define W2_E (FFN * DIM)
#define BI_E (NH * NTOK * NTOK)
#define PREP_TOTAL (WQ_E + WP_E + W1_E + W2_E + BI_E)
__global__ void prep_kernel(const float* __restrict__ qkv_w,
                            const float* __restrict__ proj_w,
                            const float* __restrict__ fc1_w,
                            const float* __restrict__ fc2_w,
                            const float* __restrict__ attn_bias,
                            const int* __restrict__ bias_idxs) {
    int idx = blockIdx.x * 256 + threadIdx.x;
    if (idx < WQ_E) {
        int k = idx / (3 * DIM), n = idx % (3 * DIM);
        g_wqh[(size_t)n * DIM + k] = __float2half(qkv_w[idx]);
        return;
    }
    idx -= WQ_E;
    if (idx < WP_E) {
        int k = idx / DIM, n = idx % DIM;
        g_wph[(size_t)n * DIM + k] = __float2half(proj_w[idx]);
        return;
    }
    idx -= WP_E;
    if (idx < W1_E) {
        int k = idx / FFN, n = idx % FFN;
        g_w1h[(size_t)n * DIM + k] = __float2half(fc1_w[idx]);
        return;
    }
    idx -= W1_E;
    if (idx < W2_E) {
        int k = idx / DIM, n = idx % DIM;
        g_w2h[(size_t)n * FFN + k] = __float2half(fc2_w[idx]);
        return;
    }
    idx -= W2_E;
    if (idx < BI_E) {
        int h = idx / (NTOK * NTOK), i = idx % (NTOK * NTOK);
        g_biasf[idx] = attn_bias[h * NTOK + bias_idxs[i]];
    }
}

// ---------------- block reduce ----------------
__device__ __forceinline__ void blockReduce2_128(float& a, float& b) {
    __shared__ float sa[4], sb_[4];
    int lane = threadIdx.x & 31, wid = threadIdx.x >> 5;
    #pragma unroll
    for (int o = 16; o > 0; o >>= 1) {
        a += __shfl_down_sync(0xffffffffu, a, o);
        b += __shfl_down_sync(0xffffffffu, b, o);
    }
    if (lane == 0) { sa[wid] = a; sb_[wid] = b; }
    __syncthreads();
    if (threadIdx.x == 0) {
        a = sa[0] + sa[1] + sa[2] + sa[3];
        b = sb_[0] + sb_[1] + sb_[2] + sb_[3];
        sa[0] = a; sb_[0] = b;
    }
    __syncthreads();
    a = sa[0]; b = sb_[0];
    __syncthreads();
}

// ---------------- LN1 + window partition -> fp16 ----------------
__global__ void ln1_window_kernel(const float* __restrict__ x,
                                  const float* __restrict__ w,
                                  const float* __restrict__ b) {
    int g = blockIdx.x;
    int win = g / NTOK, t = g % NTOK;
    int bb = win / 25, wrem = win % 25;
    int wh = wrem / 5, wwi = wrem % 5;
    int i = t / WS, j = t % WS;
    int row = wh * WS + i, col = wwi * WS + j;
    bool valid = (row < HH) && (col < WW_);
    const float* xp = x + ((size_t)bb * L + row * WW_ + col) * DIM;
    int tid = threadIdx.x;
    float vals[3];
    float s = 0.f, sq = 0.f;
    #pragma unroll
    for (int c = 0; c < 3; ++c) {
        float v = valid ? xp[tid + c * 128] : 0.f;
        vals[c] = v; s += v; sq += v * v;
    }
    blockReduce2_128(s, sq);
    float mu = s * (1.f / DIM);
    float var = sq * (1.f / DIM) - mu * mu;
    float inv = rsqrtf(var + EPSV);
    __half* op = g_xn + (size_t)g * DIM;
    #pragma unroll
    for (int c = 0; c < 3; ++c) {
        int idx = tid + c * 128;
        op[idx] = __float2half((vals[c] - mu) * inv * w[idx] + b[idx]);
    }
}

// ---------------- fused conv3x3 + BN + LN2 ----------------
__global__ void conv_bn_ln2_kernel(const float* __restrict__ cw,
                                   const float* __restrict__ bg,
                                   const float* __restrict__ bb_,
                                   const float* __restrict__ bm,
                                   const float* __restrict__ bv,
                                   const float* __restrict__ lw,
                                   const float* __restrict__ lb) {
    int g = blockIdx.x;
    int l = g % L, bb = g / L;
    int row = l / WW_, col = l % WW_;
    int tid = threadIdx.x;

    float y[3];
    float s = 0.f, sq = 0.f;
    #pragma unroll
    for (int cc3 = 0; cc3 < 3; ++cc3) {
        int c = tid + cc3 * 128;
        float acc = 0.f;
        #pragma unroll
        for (int dh = -1; dh <= 1; ++dh) {
            #pragma unroll
            for (int dw = -1; dw <= 1; ++dw) {
                int r = row + dh, cl = col + dw;
                if (r >= 0 && r < HH && cl >= 0 && cl < WW_) {
                    acc += g_xa[((size_t)bb * L + r * WW_ + cl) * DIM + c] *
                           cw[c * 9 + (dh + 1) * 3 + (dw + 1)];
                }
            }
        }
        float inv = rsqrtf(bv[c] + EPSV);
        float v = (acc - bm[c]) * inv * bg[c] + bb_[c];
        y[cc3] = v;
        g_xb[(size_t)g * DIM + c] = v;
        s += v; sq += v * v;
    }
    blockReduce2_128(s, sq);
    float mu = s * (1.f / DIM);
    float var = sq * (1.f / DIM) - mu * mu;
    float inv2 = rsqrtf(var + EPSV);
    __half* op = g_xn2 + (size_t)g * DIM;
    #pragma unroll
    for (int cc3 = 0; cc3 < 3; ++cc3) {
        int c = tid + cc3 * 128;
        op[c] = __float2half((y[cc3] - mu) * inv2 * lw[c] + lb[c]);
    }
}

// ---------------- tensor-core windowed attention, register softmax ----------------
// block = (window, head), 128 threads = 4 warps; warp owns 16 rows of S/O.
// S fragments stay in registers; softmax via quad shuffles; P fragments built
// directly from normalized S fragments (C-frag(m16n16) == A-frag(m16k16)).
#define VT_STRIDE 72
__global__ void __launch_bounds__(128) attn_kernel() {
    __shared__ __half q[64 * 32];
    __shared__ __half k[64 * 32];
    __shared__ __half vt[32 * VT_STRIDE];

    const int w = blockIdx.x;
    const int h = blockIdx.y;
    const int tid = threadIdx.x;
    const int wid = tid >> 5, lane = tid & 31;
    const uint32_t qb = s2u(q), kb = s2u(k), vb = s2u(vt);

    // zero vt (NaN-safety for padded token cols)
    #pragma unroll
    for (int i = tid; i < 32 * VT_STRIDE / 8; i += 128)
        *reinterpret_cast<uint4*>(vt + i * 8) = make_uint4(0, 0, 0, 0);
    // zero padding rows of q/k (rows 49..63) so S pad rows are finite
    for (int i = tid; i < (64 - NTOK) * 32 / 8; i += 128)
        *reinterpret_cast<uint4*>(q + NTOK * 32 + i * 8) = make_uint4(0, 0, 0, 0);
    for (int i = tid; i < (64 - NTOK) * 32 / 8; i += 128)
        *reinterpret_cast<uint4*>(k + NTOK * 32 + i * 8) = make_uint4(0, 0, 0, 0);

    const __half* base = g_qkv + (size_t)w * NTOK * (3 * DIM);
    for (int i = tid; i < NTOK * 16; i += 128) {
        int t = i / 16, d2 = i % 16;
        const __half2* pp = reinterpret_cast<const __half2*>(
            base + (size_t)t * (3 * DIM) + h * 96) + d2;
        __half2 q2 = pp[0], k2 = pp[16], v2 = pp[32];
        *reinterpret_cast<__half2*>(q + t * 32 + d2 * 2) = q2;
        *reinterpret_cast<__half2*>(k + t * 32 + d2 * 2) = k2;
        vt[(d2 * 2 + 0) * VT_STRIDE + t] = __low2half(v2);
        vt[(d2 * 2 + 1) * VT_STRIDE + t] = __high2half(v2);
    }
    __syncthreads();

    const int a_row = (lane & 7) + ((lane >> 3) & 1) * 8;
    const int a_kc  = (lane >> 4) * 8;
    const int b_nr  = (lane & 7) + ((lane >> 4) * 8);
    const int b_kc  = ((lane >> 3) & 1) * 8;
    const int erow = lane >> 2;
    const int ecol = (lane & 3) * 2;
    const int wm = wid * 16;

    // ---- S = Q @ K^T ----
    float acc[8][4];
    #pragma unroll
    for (int nt = 0; nt < 8; ++nt)
        #pragma unroll
        for (int qq = 0; qq < 4; ++qq) acc[nt][qq] = 0.f;

    #pragma unroll
    for (int ks = 0; ks < 2; ++ks) {
        uint32_t a[4];
        ldsm_x4(a, qb + (uint32_t)((wm + a_row) * 64 + (ks * 16 + a_kc) * 2));
        uint32_t b[8][2];
        #pragma unroll
        for (int np = 0; np < 4; ++np) {
            uint32_t r4[4];
            ldsm_x4(r4, kb + (uint32_t)((np * 16 + b_nr) * 64 + (ks * 16 + b_kc) * 2));
            b[np * 2 + 0][0] = r4[0]; b[np * 2 + 0][1] = r4[1];
            b[np * 2 + 1][0] = r4[2]; b[np * 2 + 1][1] = r4[3];
        }
        #pragma unroll
        for (int nt = 0; nt < 8; ++nt)
            mma_f16(acc[nt], a, b[nt]);
    }

    // ---- scale + bias + mask in registers ----
    const float scale = 0.1767766952966369f;
    const float* bf = g_biasf + (size_t)h * NTOK * NTOK;
    const int row0 = wm + erow, row1 = row0 + 8;
    const bool r0v = row0 < NTOK, r1v = row1 < NTOK;
    #pragma unroll
    for (int nt = 0; nt < 8; ++nt) {
        int col = nt * 8 + ecol;
        bool c0v = col < NTOK, c1v = (col + 1) < NTOK;
        acc[nt][0] = (r0v && c0v) ? acc[nt][0] * scale + bf[row0 * NTOK + col]     : -1e30f;
        acc[nt][1] = (r0v && c1v) ? acc[nt][1] * scale + bf[row0 * NTOK + col + 1] : -1e30f;
        acc[nt][2] = (r1v && c0v) ? acc[nt][2] * scale + bf[row1 * NTOK + col]     : -1e30f;
        acc[nt][3] = (r1v && c1v) ? acc[nt][3] * scale + bf[row1 * NTOK + col + 1] : -1e30f;
    }

    // ---- register softmax: rows row0 (regs 0,1) and row1 (regs 2,3) ----
    float m0 = -1e30f, m1 = -1e30f;
    #pragma unroll
    for (int nt = 0; nt < 8; ++nt) {
        m0 = fmaxf(m0, fmaxf(acc[nt][0], acc[nt][1]));
        m1 = fmaxf(m1, fmaxf(acc[nt][2], acc[nt][3]));
    }
    m0 = fmaxf(m0, __shfl_xor_sync(0xffffffffu, m0, 1));
    m0 = fmaxf(m0, __shfl_xor_sync(0xffffffffu, m0, 2));
    m1 = fmaxf(m1, __shfl_xor_sync(0xffffffffu, m1, 1));
    m1 = fmaxf(m1, __shfl_xor_sync(0xffffffffu, m1, 2));
    float s0 = 0.f, s1 = 0.f;
    #pragma unroll
    for (int nt = 0; nt < 8; ++nt) {
        acc[nt][0] = expf(acc[nt][0] - m0);
        acc[nt][1] = expf(acc[nt][1] - m0);
        acc[nt][2] = expf(acc[nt][2] - m1);
        acc[nt][3] = expf(acc[nt][3] - m1);
        s0 += acc[nt][0] + acc[nt][1];
        s1 += acc[nt][2] + acc[nt][3];
    }
    s0 += __shfl_xor_sync(0xffffffffu, s0, 1);
    s0 += __shfl_xor_sync(0xffffffffu, s0, 2);
    s1 += __shfl_xor_sync(0xffffffffu, s1, 1);
    s1 += __shfl_xor_sync(0xffffffffu, s1, 2);
    const float inv0 = 1.f / s0, inv1 = 1.f / s1;

    // ---- build P A-fragments directly from normalized S C-fragments ----
    uint32_t pf[4][4];
    #pragma unroll
    for (int ks = 0; ks < 4; ++ks) {
        __half2 t0 = __floats2half2_rn(acc[2 * ks][0] * inv0, acc[2 * ks][1] * inv0);
        __half2 t1 = __floats2half2_rn(acc[2 * ks][2] * inv1, acc[2 * ks][3] * inv1);
        __half2 t2 = __floats2half2_rn(acc[2 * ks + 1][0] * inv0, acc[2 * ks + 1][1] * inv0);
        __half2 t3 = __floats2half2_rn(acc[2 * ks + 1][2] * inv1, acc[2 * ks + 1][3] * inv1);
        pf[ks][0] = *reinterpret_cast<uint32_t*>(&t0);
        pf[ks][1] = *reinterpret_cast<uint32_t*>(&t1);
        pf[ks][2] = *reinterpret_cast<uint32_t*>(&t2);
        pf[ks][3] = *reinterpret_cast<uint32_t*>(&t3);
    }

    // ---- O = P @ V ----
    float oacc[4][4];
    #pragma unroll
    for (int nt = 0; nt < 4; ++nt)
        #pragma unroll
        for (int qq = 0; qq < 4; ++qq) oacc[nt][qq] = 0.f;

    #pragma unroll
    for (int ks = 0; ks < 4; ++ks) {
        uint32_t b[4][2];
        #pragma unroll
        for (int np = 0; np < 2; ++np) {
            uint32_t r4[4];
            ldsm_x4(r4, vb + (uint32_t)((np * 16 + b_nr) * (VT_STRIDE * 2) + (ks * 16 + b_kc) * 2));
            b[np * 2 + 0][0] = r4[0]; b[np * 2 + 0][1] = r4[1];
            b[np * 2 + 1][0] = r4[2]; b[np * 2 + 1][1] = r4[3];
        }
        #pragma unroll
        for (int nt = 0; nt < 4; ++nt)
            mma_f16(oacc[nt], pf[ks], b[nt]);
    }

    #pragma unroll
    for (int nt = 0; nt < 4; ++nt) {
        #pragma unroll
        for (int hh = 0; hh < 2; ++hh) {
            int row = wm + erow + hh * 8;
            if (row >= NTOK) continue;
            int col = nt * 8 + ecol;
            __half2 hp = __floats2half2_rn(oacc[nt][hh * 2 + 0], oacc[nt][hh * 2 + 1]);
            *reinterpret_cast<__half2*>(
                g_ao + ((size_t)w * NTOK + row) * DIM + h * HD + col) = hp;
        }
    }
}

// ---------------- launch ----------------
extern "C" void kernel_launch(void* const* d_in, const int* in_sizes, int n_in,
                              void* d_out, int out_size) {
    const float* x         = (const float*)d_in[0];
    const float* ln1_w     = (const float*)d_in[1];
    const float* ln1_b     = (const float*)d_in[2];
    const float* qkv_w     = (const float*)d_in[3];
    const float* qkv_b     = (const float*)d_in[4];
    const float* proj_w    = (const float*)d_in[5];
    const float* proj_b    = (const float*)d_in[6];
    const float* attn_bias = (const float*)d_in[7];
    const int*   bias_idxs = (const int*)d_in[8];
    const float* conv_w    = (const float*)d_in[9];
    const float* bn_g      = (const float*)d_in[10];
    const float* bn_b      = (const float*)d_in[11];
    const float* bn_m      = (const float*)d_in[12];
    const float* bn_v      = (const float*)d_in[13];
    const float* ln2_w     = (const float*)d_in[14];
    const float* ln2_b     = (const float*)d_in[15];
    const float* fc1_w     = (const float*)d_in[16];
    const float* fc1_b     = (const float*)d_in[17];
    const float* fc2_w     = (const float*)d_in[18];
    const float* fc2_b     = (const float*)d_in[19];
    float* out = (float*)d_out;

    __half *xn, *qkv, *ao, *xn2, *hbuf, *wqh, *wph, *w1h, *w2h;
    float *xa, *xb;
    cudaGetSymbolAddress((void**)&xn,  g_xn);
    cudaGetSymbolAddress((void**)&qkv, g_qkv);
    cudaGetSymbolAddress((void**)&ao,  g_ao);
    cudaGetSymbolAddress((void**)&xa,  g_xa);
    cudaGetSymbolAddress((void**)&xb,  g_xb);
    cudaGetSymbolAddress((void**)&xn2, g_xn2);
    cudaGetSymbolAddress((void**)&hbuf, g_h);
    cudaGetSymbolAddress((void**)&wqh, g_wqh);
    cudaGetSymbolAddress((void**)&wph, g_wph);
    cudaGetSymbolAddress((void**)&w1h, g_w1h);
    cudaGetSymbolAddress((void**)&w2h, g_w2h);

    cudaFuncSetAttribute(hmm_kernel<0>, cudaFuncAttributeMaxDynamicSharedMemorySize, HMM_SMEM_BYTES);
    cudaFuncSetAttribute(hmm_kernel<1>, cudaFuncAttributeMaxDynamicSharedMemorySize, HMM_SMEM_BYTES);
    cudaFuncSetAttribute(hmm_kernel<2>, cudaFuncAttributeMaxDynamicSharedMemorySize, HMM_SMEM_BYTES);
    cudaFuncSetAttribute(hmm_kernel<3>, cudaFuncAttributeMaxDynamicSharedMemorySize, HMM_SMEM_BYTES);

    // 0) fused prep
    prep_kernel<<<(PREP_TOTAL + 255) / 256, 256>>>(qkv_w, proj_w, fc1_w, fc2_w,
                                                   attn_bias, bias_idxs);

    // 1) LN1 + window partition (fp16)
    ln1_window_kernel<<<TOKENS, 128>>>(x, ln1_w, ln1_b);

    // 2) qkv GEMM (fp16)
    {
        dim3 grid((3 * DIM) / 128, MPAD / 128);
        hmm_kernel<0><<<grid, 256, HMM_SMEM_BYTES>>>(xn, wqh, qkv_b, qkv, nullptr,
                                                     TOKENS, 3 * DIM, DIM);
    }

    // 3) windowed attention (tensor cores, register softmax)
    {
        dim3 grid(NWIN, NH);
        attn_kernel<<<grid, 128>>>();
    }

    // 4) proj GEMM (fp16) + fused scatter/residual -> g_xa
    {
        dim3 grid(DIM / 128, MPAD / 128);
        hmm_kernel<1><<<grid, 256, HMM_SMEM_BYTES>>>(ao, wph, proj_b, xa, x,
                                                     TOKENS, DIM, DIM);
    }

    // 5) conv + BN + LN2 (fused)
    conv_bn_ln2_kernel<<<BL, 128>>>(conv_w, bn_g, bn_b, bn_m, bn_v, ln2_w, ln2_b);

    // 6) fc1 + gelu (fp16)
    {
        dim3 grid(FFN / 128, BL / 128);
        hmm_kernel<2><<<grid, 256, HMM_SMEM_BYTES>>>(xn2, w1h, fc1_b, hbuf, nullptr,
                                                     BL, FFN, DIM);
    }

    // 7) fc2 + residual -> out
    {
        dim3 grid(DIM / 128, BL / 128);
        hmm_kernel<3><<<grid, 256, HMM_SMEM_BYTES>>>(hbuf, w2h, fc2_b, out, xb,
                                                     BL, DIM, FFN);
    }
}